// round 6
// baseline (speedup 1.0000x reference)
#include <cuda_runtime.h>
#include <cuda_bf16.h>
#include <math.h>
#include <cstdint>

// ---------------- problem constants ----------------
#define BB       256
#define DMODEL   2048
#define DINNER   8192
#define DSTATE   16
#define DTRANK   128
#define XPN      (DTRANK + 2*DSTATE)   // 160

// ---------------- scratch (device globals; no allocation) ----------------
__device__ float g_xz [BB * 2 * DINNER];   // xi | z
__device__ float g_xc [BB * DINNER];
__device__ float g_xdb[BB * XPN];
__device__ float g_dt [BB * DINNER];
__device__ float g_y  [BB * DINNER];
__device__ float g_A  [DINNER * DSTATE];

// ---------------- helpers ----------------
__device__ __forceinline__ uint32_t smem_u32(const void* p) {
    uint32_t a;
    asm("{ .reg .u64 t; cvta.to.shared.u64 t, %1; cvt.u32.u64 %0, t; }" : "=r"(a) : "l"(p));
    return a;
}

__device__ __forceinline__ void ldmx4(uint32_t* r, uint32_t addr) {
    asm volatile("ldmatrix.sync.aligned.m8n8.x4.shared.b16 {%0,%1,%2,%3}, [%4];"
        : "=r"(r[0]), "=r"(r[1]), "=r"(r[2]), "=r"(r[3]) : "r"(addr));
}

__device__ __forceinline__ void mma16816(float* d, const uint32_t* a, const uint32_t* b) {
    asm volatile(
        "mma.sync.aligned.m16n8k16.row.col.f32.bf16.bf16.f32 "
        "{%0,%1,%2,%3}, {%4,%5,%6,%7}, {%8,%9}, {%0,%1,%2,%3};"
        : "+f"(d[0]), "+f"(d[1]), "+f"(d[2]), "+f"(d[3])
        : "r"(a[0]), "r"(a[1]), "r"(a[2]), "r"(a[3]), "r"(b[0]), "r"(b[1]));
}

// split float4 into bf16 hi + bf16 lo (residual), write 4 elems each
__device__ __forceinline__ void split_store(__nv_bfloat16* th, __nv_bfloat16* tl,
                                            const float4& v) {
    __nv_bfloat162 h01 = __floats2bfloat162_rn(v.x, v.y);
    __nv_bfloat162 h23 = __floats2bfloat162_rn(v.z, v.w);
    float lx = v.x - __bfloat162float(h01.x);
    float ly = v.y - __bfloat162float(h01.y);
    float lz = v.z - __bfloat162float(h23.x);
    float lw = v.w - __bfloat162float(h23.y);
    __nv_bfloat162 l01 = __floats2bfloat162_rn(lx, ly);
    __nv_bfloat162 l23 = __floats2bfloat162_rn(lz, lw);
    uint2 hp = make_uint2(*(uint32_t*)&h01, *(uint32_t*)&h23);
    uint2 lp = make_uint2(*(uint32_t*)&l01, *(uint32_t*)&l23);
    *(uint2*)th = hp;
    *(uint2*)tl = lp;
}

// ---------------- HMMA bf16 hi/lo GEMM:  C[M,N] (+)= A[M,K] * B[N,K]^T ------
// 128 threads, CTA tile 64x128x32, 4 warps (1m x 4n, warp tile 64x32).
// Double-buffered smem, inline fp32->bf16 hi/lo split, 3-product compensation.
// EPI: 0 = store, 1 = atomicAdd (split-K)
#define GBM 64
#define GBN 128
#define GBK 32
#define GSK 40                               // padded bf16 stride
#define A_LO   (GBM * GSK)                   // 2560
#define B_HI   (2 * GBM * GSK)               // 5120
#define B_LO   (B_HI + GBN * GSK)            // 10240
#define STG_ELEMS (2*GBM*GSK + 2*GBN*GSK)    // 15360
#define STG_BYTES (STG_ELEMS * 2)            // 30720

template<int EPI, int SPLITK>
__global__ void __launch_bounds__(128, 3)
hmma_gemm(const float* __restrict__ A, int lda,
          const float* __restrict__ B, int ldb,
          float* __restrict__ C, int ldc, int K)
{
    extern __shared__ __nv_bfloat16 sm[];

    const int tid = threadIdx.x;
    const int m0  = blockIdx.x * GBM;
    const int n0  = blockIdx.y * GBN;
    const int kChunk = K / SPLITK;
    const int kb  = blockIdx.z * kChunk;
    const int iters = kChunk / GBK;

    // ---- loader: 384 half-rows (16 floats) over 128 threads -> 3 units ----
    const float* gptr[3];
    int soff[3], lod[3];
    #pragma unroll
    for (int j = 0; j < 3; j++) {
        int u = tid + j * 128;
        int row = u >> 1, h = (u & 1) * 16;
        if (row < GBM) {
            gptr[j] = A + (size_t)(m0 + row) * lda + kb + h;
            soff[j] = row * GSK + h;
            lod[j]  = GBM * GSK;
        } else {
            int br = row - GBM;
            gptr[j] = B + (size_t)(n0 + br) * ldb + kb + h;
            soff[j] = B_HI + br * GSK + h;
            lod[j]  = GBN * GSK;
        }
    }

    float4 r[3][4];
    #pragma unroll
    for (int j = 0; j < 3; j++)
        #pragma unroll
        for (int q = 0; q < 4; q++)
            r[j][q] = *(const float4*)(gptr[j] + q * 4);

    // store iter 0 into stage 0
    #pragma unroll
    for (int j = 0; j < 3; j++)
        #pragma unroll
        for (int q = 0; q < 4; q++)
            split_store(sm + soff[j] + q*4, sm + soff[j] + lod[j] + q*4, r[j][q]);

    // prefetch iter 1
    if (iters > 1) {
        #pragma unroll
        for (int j = 0; j < 3; j++) {
            gptr[j] += GBK;
            #pragma unroll
            for (int q = 0; q < 4; q++)
                r[j][q] = *(const float4*)(gptr[j] + q * 4);
        }
    }

    // ---- compute mapping ----
    const int w    = tid >> 5;
    const int lane = tid & 31;
    const int wn   = w * 32;
    const int g    = lane >> 3;
    const int rr   = lane & 7;
    const uint32_t usm = smem_u32(sm);

    float acc[4][4][4];
    #pragma unroll
    for (int i = 0; i < 4; i++)
        #pragma unroll
        for (int j = 0; j < 4; j++)
            #pragma unroll
            for (int c = 0; c < 4; c++) acc[i][j][c] = 0.0f;

    __syncthreads();

    for (int it = 0; it < iters; ++it) {
        const int s = it & 1;

        // (a) store iter it+1 into stage s^1 (that stage drained last iter)
        if (it + 1 < iters) {
            __nv_bfloat16* st = sm + (s ^ 1) * STG_ELEMS;
            #pragma unroll
            for (int j = 0; j < 3; j++)
                #pragma unroll
                for (int q = 0; q < 4; q++)
                    split_store(st + soff[j] + q*4, st + soff[j] + lod[j] + q*4, r[j][q]);
        }
        // (b) LDG prefetch iter it+2
        if (it + 2 < iters) {
            #pragma unroll
            for (int j = 0; j < 3; j++) {
                gptr[j] += GBK;
                #pragma unroll
                for (int q = 0; q < 4; q++)
                    r[j][q] = *(const float4*)(gptr[j] + q * 4);
            }
        }

        // (c) compute from stage s
        const uint32_t uS  = usm + (uint32_t)s * STG_BYTES;
        const uint32_t uAh = uS;
        const uint32_t uAl = uS + A_LO * 2;
        const uint32_t uBh = uS + B_HI * 2;
        const uint32_t uBl = uS + B_LO * 2;

        #pragma unroll
        for (int ks = 0; ks < 2; ks++) {
            const int k16  = ks * 16;
            const int kcol = k16 + (g >> 1) * 8;
            uint32_t bh[4][2], bl[4][2];
            #pragma unroll
            for (int pi = 0; pi < 2; pi++) {
                int browb = wn + pi * 16 + (g & 1) * 8 + rr;
                uint32_t off = (uint32_t)(browb * GSK + kcol) * 2;
                uint32_t t[4];
                ldmx4(t, uBh + off);
                bh[pi*2+0][0] = t[0]; bh[pi*2+0][1] = t[2];
                bh[pi*2+1][0] = t[1]; bh[pi*2+1][1] = t[3];
                ldmx4(t, uBl + off);
                bl[pi*2+0][0] = t[0]; bl[pi*2+0][1] = t[2];
                bl[pi*2+1][0] = t[1]; bl[pi*2+1][1] = t[3];
            }
            #pragma unroll
            for (int mi = 0; mi < 4; mi++) {
                int arow = mi * 16 + (g & 1) * 8 + rr;
                uint32_t off = (uint32_t)(arow * GSK + kcol) * 2;
                uint32_t ah[4], al[4];
                ldmx4(ah, uAh + off);
                ldmx4(al, uAl + off);
                #pragma unroll
                for (int ni = 0; ni < 4; ni++) {
                    mma16816(acc[mi][ni], ah, bh[ni]);
                    mma16816(acc[mi][ni], al, bh[ni]);
                    mma16816(acc[mi][ni], ah, bl[ni]);
                }
            }
        }
        __syncthreads();
    }

    // ---- epilogue ----
    const int erow = lane >> 2;
    const int ecol = (lane & 3) * 2;
    #pragma unroll
    for (int mi = 0; mi < 4; mi++) {
        #pragma unroll
        for (int ni = 0; ni < 4; ni++) {
            int r0 = m0 + mi * 16 + erow;
            int c0 = n0 + wn + ni * 8 + ecol;
            float* p0 = C + (size_t)r0 * ldc + c0;
            float* p1 = C + (size_t)(r0 + 8) * ldc + c0;
            if (EPI == 0) {
                *(float2*)p0 = make_float2(acc[mi][ni][0], acc[mi][ni][1]);
                *(float2*)p1 = make_float2(acc[mi][ni][2], acc[mi][ni][3]);
            } else {
                atomicAdd(p0,     acc[mi][ni][0]);
                atomicAdd(p0 + 1, acc[mi][ni][1]);
                atomicAdd(p1,     acc[mi][ni][2]);
                atomicAdd(p1 + 1, acc[mi][ni][3]);
            }
        }
    }
}

// ---------------- small helpers ----------------
__global__ void zero_kernel(float* __restrict__ p, int n) {
    int i = blockIdx.x * blockDim.x + threadIdx.x;
    if (i < n) p[i] = 0.0f;
}

__global__ void precompute_A_kernel(const float* __restrict__ A_log) {
    int i = blockIdx.x * blockDim.x + threadIdx.x;
    if (i < DINNER * DSTATE) g_A[i] = -expf(A_log[i]);
}

// ---------------- fp32 tiled SGEMM (small GEMMs) ----------------
template<int BM, int BN, int BK, int TM, int TN, int EPI>
__global__ void __launch_bounds__((BM/TM)*(BN/TN))
sgemm_nt(const float* __restrict__ A, int lda,
         const float* __restrict__ Bm, int ldb,
         float* __restrict__ C, int ldc,
         int M, int N, int K, int kChunk,
         const float* __restrict__ bias)
{
    constexpr int THREADS = (BM/TM)*(BN/TN);
    constexpr int KQ = BK / 4;
    constexpr int A4 = BM * BK / 4;
    constexpr int B4 = BN * BK / 4;

    __shared__ float As[BK][BM];
    __shared__ float Bs[BK][BN];

    const int tid = threadIdx.x;
    const int n0  = blockIdx.x * BN;
    const int m0  = blockIdx.y * BM;
    const int kb  = blockIdx.z * kChunk;
    const int ke  = (kb + kChunk < K) ? (kb + kChunk) : K;

    const int tc = tid % (BN / TN);
    const int tr = tid / (BN / TN);

    float acc[TM][TN];
    #pragma unroll
    for (int i = 0; i < TM; i++)
        #pragma unroll
        for (int j = 0; j < TN; j++) acc[i][j] = 0.0f;

    for (int k0 = kb; k0 < ke; k0 += BK) {
        #pragma unroll
        for (int i = tid; i < A4; i += THREADS) {
            int m  = i / KQ;
            int kq = i % KQ;
            float4 v = *(const float4*)&A[(size_t)(m0 + m) * lda + k0 + kq * 4];
            As[kq*4+0][m] = v.x; As[kq*4+1][m] = v.y;
            As[kq*4+2][m] = v.z; As[kq*4+3][m] = v.w;
        }
        #pragma unroll
        for (int i = tid; i < B4; i += THREADS) {
            int n  = i / KQ;
            int kq = i % KQ;
            float4 v = *(const float4*)&Bm[(size_t)(n0 + n) * ldb + k0 + kq * 4];
            Bs[kq*4+0][n] = v.x; Bs[kq*4+1][n] = v.y;
            Bs[kq*4+2][n] = v.z; Bs[kq*4+3][n] = v.w;
        }
        __syncthreads();

        #pragma unroll
        for (int kk = 0; kk < BK; kk++) {
            float a[TM], b[TN];
            #pragma unroll
            for (int i = 0; i < TM; i++) a[i] = As[kk][tr*TM + i];
            #pragma unroll
            for (int j = 0; j < TN; j++) b[j] = Bs[kk][tc*TN + j];
            #pragma unroll
            for (int i = 0; i < TM; i++)
                #pragma unroll
                for (int j = 0; j < TN; j++)
                    acc[i][j] = fmaf(a[i], b[j], acc[i][j]);
        }
        __syncthreads();
    }

    #pragma unroll
    for (int i = 0; i < TM; i++) {
        int m = m0 + tr*TM + i;
        #pragma unroll
        for (int j = 0; j < TN; j++) {
            int n = n0 + tc*TN + j;
            float v = acc[i][j];
            if (EPI == 0) {
                C[(size_t)m * ldc + n] = v;
            } else if (EPI == 1) {
                atomicAdd(&C[(size_t)m * ldc + n], v);
            } else {
                float x = v + bias[n];
                float r2 = fmaxf(x, 0.0f) + log1pf(__expf(-fabsf(x)));
                C[(size_t)m * ldc + n] = r2;
            }
        }
    }
}

// ---------------- conv window shift + SiLU ----------------
__global__ void conv_kernel(const float* __restrict__ cs_in,
                            const float* __restrict__ conv_w,
                            const float* __restrict__ conv_b,
                            float* __restrict__ cs_out)
{
    int idx = blockIdx.x * blockDim.x + threadIdx.x;
    int b = idx >> 13;
    int d = idx & (DINNER - 1);
    float4 cs = ((const float4*)cs_in)[idx];
    float4 w  = ((const float4*)conv_w)[d];
    float xi  = g_xz[(size_t)b * (2*DINNER) + d];
    float s = cs.y*w.x + cs.z*w.y + cs.w*w.z + xi*w.w + conv_b[d];
    float sig = 1.0f / (1.0f + __expf(-s));
    g_xc[idx] = s * sig;
    ((float4*)cs_out)[idx] = make_float4(cs.y, cs.z, cs.w, xi);
}

// ---------------- SSM state update + y ----------------
__global__ void ssm_kernel(const float* __restrict__ ssm_in,
                           const float* __restrict__ D_param,
                           float* __restrict__ ssm_out)
{
    __shared__ float bm[DSTATE], cm[DSTATE];
    const int b = blockIdx.y;
    const int d = blockIdx.x * blockDim.x + threadIdx.x;
    if (threadIdx.x < 2*DSTATE) {
        float v = g_xdb[b * XPN + DTRANK + threadIdx.x];
        if (threadIdx.x < DSTATE) bm[threadIdx.x] = v;
        else                      cm[threadIdx.x - DSTATE] = v;
    }
    __syncthreads();

    const int bd = b * DINNER + d;
    const float dtv = g_dt[bd];
    const float xcv = g_xc[bd];
    const float xdt = xcv * dtv;
    const size_t base = (size_t)bd * DSTATE;

    float yacc = 0.0f;
    #pragma unroll
    for (int n = 0; n < DSTATE; n += 4) {
        float4 a  = *(const float4*)&g_A[d * DSTATE + n];
        float4 st = *(const float4*)&ssm_in[base + n];
        float4 ns;
        ns.x = st.x * __expf(a.x * dtv) + xdt * bm[n+0];
        ns.y = st.y * __expf(a.y * dtv) + xdt * bm[n+1];
        ns.z = st.z * __expf(a.z * dtv) + xdt * bm[n+2];
        ns.w = st.w * __expf(a.w * dtv) + xdt * bm[n+3];
        yacc += ns.x * cm[n+0] + ns.y * cm[n+1] + ns.z * cm[n+2] + ns.w * cm[n+3];
        *(float4*)&ssm_out[base + n] = ns;
    }
    yacc += D_param[d] * xcv;
    float zv = g_xz[(size_t)b * (2*DINNER) + DINNER + d];
    yacc *= zv / (1.0f + __expf(-zv));
    g_y[bd] = yacc;
}

// ---------------- launch ----------------
extern "C" void kernel_launch(void* const* d_in, const int* in_sizes, int n_in,
                              void* d_out, int out_size)
{
    const float* x       = (const float*)d_in[0];
    const float* cs_in   = (const float*)d_in[1];
    const float* ssm_in  = (const float*)d_in[2];
    const float* W_in    = (const float*)d_in[3];
    const float* conv_w  = (const float*)d_in[4];
    const float* conv_b  = (const float*)d_in[5];
    const float* W_xproj = (const float*)d_in[6];
    const float* W_dt    = (const float*)d_in[7];
    const float* b_dt    = (const float*)d_in[8];
    const float* A_log   = (const float*)d_in[9];
    const float* D_param = (const float*)d_in[10];
    const float* W_out   = (const float*)d_in[11];

    float* out     = (float*)d_out;
    float* cs_out  = out + (size_t)BB * DMODEL;
    float* ssm_out = cs_out + (size_t)BB * DINNER * 4;

    void *p_xz, *p_xc, *p_xdb, *p_dt, *p_y;
    cudaGetSymbolAddress(&p_xz,  g_xz);
    cudaGetSymbolAddress(&p_xc,  g_xc);
    cudaGetSymbolAddress(&p_xdb, g_xdb);
    cudaGetSymbolAddress(&p_dt,  g_dt);
    cudaGetSymbolAddress(&p_y,   g_y);

    const int HSM = 2 * STG_BYTES;   // 61440 bytes
    cudaFuncSetAttribute(hmma_gemm<0,1>, cudaFuncAttributeMaxDynamicSharedMemorySize, HSM);
    cudaFuncSetAttribute(hmma_gemm<1,4>, cudaFuncAttributeMaxDynamicSharedMemorySize, HSM);

    // zero split-K accumulation targets
    zero_kernel<<<(BB*XPN + 255)/256, 256>>>((float*)p_xdb, BB*XPN);
    zero_kernel<<<(BB*DMODEL + 255)/256, 256>>>(out, BB*DMODEL);
    precompute_A_kernel<<<(DINNER*DSTATE + 255)/256, 256>>>(A_log);

    // GEMM1: xz[256,16384] = x @ W_in^T   (HMMA, grid m-fastest for W reuse)
    hmma_gemm<0,1><<<dim3(BB/GBM, (2*DINNER)/GBN, 1), 128, HSM>>>(
        x, DMODEL, W_in, DMODEL, (float*)p_xz, 2*DINNER, DMODEL);

    // conv + SiLU
    conv_kernel<<<(BB*DINNER)/256, 256>>>(cs_in, conv_w, conv_b, cs_out);

    // GEMM3: x_db[256,160] = xc @ W_xproj^T  (fp32, BK=32, split-K=16, atomic)
    sgemm_nt<64,32,32,4,4,1><<<dim3(XPN/32, BB/64, 16), 128>>>(
        (const float*)p_xc, DINNER, W_xproj, DINNER, (float*)p_xdb, XPN,
        BB, XPN, DINNER, DINNER/16, nullptr);

    // GEMM4: dt[256,8192] = softplus(x_db[:, :128] @ W_dt^T + b_dt)  (fp32, BK=32)
    sgemm_nt<64,64,32,4,4,2><<<dim3(DINNER/64, BB/64, 1), 256>>>(
        (const float*)p_xdb, XPN, W_dt, DTRANK, (float*)p_dt, DINNER,
        BB, DINNER, DTRANK, DTRANK, b_dt);

    // SSM update + y
    ssm_kernel<<<dim3(DINNER/256, BB), 256>>>(ssm_in, D_param, ssm_out);

    // GEMM6: out[256,2048] = y @ W_out^T  (HMMA, split-K=4, atomic)
    hmma_gemm<1,4><<<dim3(BB/GBM, DMODEL/GBN, 4), 128, HSM>>>(
        (const float*)p_y, DINNER, W_out, DINNER, out, DMODEL, DINNER);
}

// round 7
// speedup vs baseline: 1.0639x; 1.0639x over previous
#include <cuda_runtime.h>
#include <cuda_bf16.h>
#include <math.h>
#include <cstdint>

// ---------------- problem constants ----------------
#define BB       256
#define DMODEL   2048
#define DINNER   8192
#define DSTATE   16
#define DTRANK   128
#define XPN      (DTRANK + 2*DSTATE)   // 160

// ---------------- scratch (device globals; no allocation) ----------------
__device__ float g_xz [BB * 2 * DINNER];   // xi | z
__device__ float g_xc [BB * DINNER];
__device__ float g_xdb[BB * XPN];
__device__ float g_dt [BB * DINNER];
__device__ float g_A  [DINNER * DSTATE];

// bf16 hi/lo split tensors (pre-split in gmem)
__device__ __nv_bfloat16 g_xhi  [BB * DMODEL];
__device__ __nv_bfloat16 g_xlo  [BB * DMODEL];
__device__ __nv_bfloat16 g_winhi[2 * DINNER * DMODEL];
__device__ __nv_bfloat16 g_winlo[2 * DINNER * DMODEL];
__device__ __nv_bfloat16 g_wouthi[DMODEL * DINNER];
__device__ __nv_bfloat16 g_woutlo[DMODEL * DINNER];
__device__ __nv_bfloat16 g_yhi  [BB * DINNER];
__device__ __nv_bfloat16 g_ylo  [BB * DINNER];

// ---------------- helpers ----------------
__device__ __forceinline__ uint32_t smem_u32(const void* p) {
    uint32_t a;
    asm("{ .reg .u64 t; cvta.to.shared.u64 t, %1; cvt.u32.u64 %0, t; }" : "=r"(a) : "l"(p));
    return a;
}

__device__ __forceinline__ void ldmx4(uint32_t* r, uint32_t addr) {
    asm volatile("ldmatrix.sync.aligned.m8n8.x4.shared.b16 {%0,%1,%2,%3}, [%4];"
        : "=r"(r[0]), "=r"(r[1]), "=r"(r[2]), "=r"(r[3]) : "r"(addr));
}

__device__ __forceinline__ void mma16816(float* d, const uint32_t* a, const uint32_t* b) {
    asm volatile(
        "mma.sync.aligned.m16n8k16.row.col.f32.bf16.bf16.f32 "
        "{%0,%1,%2,%3}, {%4,%5,%6,%7}, {%8,%9}, {%0,%1,%2,%3};"
        : "+f"(d[0]), "+f"(d[1]), "+f"(d[2]), "+f"(d[3])
        : "r"(a[0]), "r"(a[1]), "r"(a[2]), "r"(a[3]), "r"(b[0]), "r"(b[1]));
}

__device__ __forceinline__ void cp16(uint32_t s, const void* g) {
    asm volatile("cp.async.cg.shared.global [%0], [%1], 16;" :: "r"(s), "l"(g));
}
#define CP_COMMIT() asm volatile("cp.async.commit_group;" ::: "memory")
#define CP_WAIT(n)  asm volatile("cp.async.wait_group %0;" :: "n"(n) : "memory")

// ---------------- HMMA bf16 hi/lo GEMM (pre-split operands) ----------------
// C[M,N] (+)= (Ah+Al)[M,K] * (Bh+Bl)[N,K]^T, 3-product compensation.
// 256 threads, tile 128x128x32, cp.async double-buffered. iters must be >= 2.
// EPI: 0 = store, 1 = atomicAdd (split-K)
#define GBM 128
#define GBN 128
#define GBK 32
#define GSK 40                        // padded bf16 row stride (conflict-free ldsm)
#define T_ELEMS (GBM * GSK)           // 5120 elems per operand block
#define TBYTES  (T_ELEMS * 2)         // 10240
#define STG_BYTES (4 * TBYTES)        // 40960 per stage

template<int EPI, int SPLITK>
__global__ void __launch_bounds__(256, 2)
hmma_gemm(const __nv_bfloat16* __restrict__ Ah, const __nv_bfloat16* __restrict__ Al,
          const __nv_bfloat16* __restrict__ Bh, const __nv_bfloat16* __restrict__ Bl,
          float* __restrict__ C, int ldc, int K)
{
    extern __shared__ __nv_bfloat16 sm[];

    const int tid = threadIdx.x;
    const int n0  = blockIdx.x * GBN;
    const int m0  = blockIdx.y * GBM;
    const int kChunk = K / SPLITK;
    const int kb  = blockIdx.z * kChunk;
    const int iters = kChunk / GBK;   // >= 2 for all uses here

    const uint32_t usm = smem_u32(sm);

    // loader: thread -> rows (tid>>2) and (tid>>2)+64, 16B chunk (tid&3)
    const int lrow = tid >> 2;
    const int lch  = (tid & 3) * 8;     // bf16 elem offset of the 16B chunk

    const uint32_t d0 = (uint32_t)(lrow * GSK + lch) * 2;
    const uint32_t d1 = (uint32_t)((lrow + 64) * GSK + lch) * 2;

    auto issue = [&](uint32_t sbase, int koff) {
        size_t a0 = (size_t)(m0 + lrow)      * K + koff + lch;
        size_t a1 = (size_t)(m0 + lrow + 64) * K + koff + lch;
        size_t b0 = (size_t)(n0 + lrow)      * K + koff + lch;
        size_t b1 = (size_t)(n0 + lrow + 64) * K + koff + lch;
        cp16(sbase + d0,            Ah + a0);
        cp16(sbase + d1,            Ah + a1);
        cp16(sbase + d0 + TBYTES,   Al + a0);
        cp16(sbase + d1 + TBYTES,   Al + a1);
        cp16(sbase + d0 + 2*TBYTES, Bh + b0);
        cp16(sbase + d1 + 2*TBYTES, Bh + b1);
        cp16(sbase + d0 + 3*TBYTES, Bl + b0);
        cp16(sbase + d1 + 3*TBYTES, Bl + b1);
    };

    // prologue: both stages in flight
    issue(usm, kb);
    CP_COMMIT();
    issue(usm + STG_BYTES, kb + GBK);
    CP_COMMIT();

    // compute mapping: 8 warps, 2m x 4n, warp tile 64x32
    const int w    = tid >> 5;
    const int lane = tid & 31;
    const int wm   = (w & 1) * 64;
    const int wn   = (w >> 1) * 32;
    const int g    = lane >> 3;
    const int rr   = lane & 7;

    float acc[4][4][4];
    #pragma unroll
    for (int i = 0; i < 4; i++)
        #pragma unroll
        for (int j = 0; j < 4; j++)
            #pragma unroll
            for (int c = 0; c < 4; c++) acc[i][j][c] = 0.0f;

    for (int it = 0; it < iters; ++it) {
        const int s = it & 1;
        if (it + 1 < iters) { CP_WAIT(1); } else { CP_WAIT(0); }
        __syncthreads();

        const uint32_t uS  = usm + (uint32_t)s * STG_BYTES;
        const uint32_t uAh = uS;
        const uint32_t uAl = uS + TBYTES;
        const uint32_t uBh = uS + 2*TBYTES;
        const uint32_t uBl = uS + 3*TBYTES;

        #pragma unroll
        for (int ks = 0; ks < 2; ks++) {
            const int kcol = ks * 16 + (g >> 1) * 8;
            uint32_t bh[4][2], bl[4][2];
            #pragma unroll
            for (int pi = 0; pi < 2; pi++) {
                int browb = wn + pi * 16 + (g & 1) * 8 + rr;
                uint32_t off = (uint32_t)(browb * GSK + kcol) * 2;
                uint32_t t[4];
                ldmx4(t, uBh + off);
                bh[pi*2+0][0] = t[0]; bh[pi*2+0][1] = t[2];
                bh[pi*2+1][0] = t[1]; bh[pi*2+1][1] = t[3];
                ldmx4(t, uBl + off);
                bl[pi*2+0][0] = t[0]; bl[pi*2+0][1] = t[2];
                bl[pi*2+1][0] = t[1]; bl[pi*2+1][1] = t[3];
            }
            #pragma unroll
            for (int mi = 0; mi < 4; mi++) {
                int arow = wm + mi * 16 + (g & 1) * 8 + rr;
                uint32_t off = (uint32_t)(arow * GSK + kcol) * 2;
                uint32_t ah[4], al[4];
                ldmx4(ah, uAh + off);
                ldmx4(al, uAl + off);
                #pragma unroll
                for (int ni = 0; ni < 4; ni++) {
                    mma16816(acc[mi][ni], ah, bh[ni]);
                    mma16816(acc[mi][ni], al, bh[ni]);
                    mma16816(acc[mi][ni], ah, bl[ni]);
                }
            }
        }
        __syncthreads();   // all warps done reading stage s before refill
        if (it + 2 < iters) {
            issue(usm + (uint32_t)s * STG_BYTES, kb + (it + 2) * GBK);
            CP_COMMIT();
        }
    }

    // ---- epilogue ----
    const int erow = lane >> 2;
    const int ecol = (lane & 3) * 2;
    #pragma unroll
    for (int mi = 0; mi < 4; mi++) {
        #pragma unroll
        for (int ni = 0; ni < 4; ni++) {
            int r0 = m0 + wm + mi * 16 + erow;
            int c0 = n0 + wn + ni * 8 + ecol;
            float* p0 = C + (size_t)r0 * ldc + c0;
            float* p1 = C + (size_t)(r0 + 8) * ldc + c0;
            if (EPI == 0) {
                *(float2*)p0 = make_float2(acc[mi][ni][0], acc[mi][ni][1]);
                *(float2*)p1 = make_float2(acc[mi][ni][2], acc[mi][ni][3]);
            } else {
                atomicAdd(p0,     acc[mi][ni][0]);
                atomicAdd(p0 + 1, acc[mi][ni][1]);
                atomicAdd(p1,     acc[mi][ni][2]);
                atomicAdd(p1 + 1, acc[mi][ni][3]);
            }
        }
    }
}

// ---------------- small helpers ----------------
__global__ void zero_kernel(float* __restrict__ p, int n) {
    int i = blockIdx.x * blockDim.x + threadIdx.x;
    if (i < n) p[i] = 0.0f;
}

__global__ void precompute_A_kernel(const float* __restrict__ A_log) {
    int i = blockIdx.x * blockDim.x + threadIdx.x;
    if (i < DINNER * DSTATE) g_A[i] = -expf(A_log[i]);
}

// split fp32 -> bf16 hi + bf16 lo (residual), float4-vectorized
__global__ void split_bf16_kernel(const float4* __restrict__ in,
                                  __nv_bfloat162* __restrict__ hi,
                                  __nv_bfloat162* __restrict__ lo, int n4) {
    int i = blockIdx.x * blockDim.x + threadIdx.x;
    if (i >= n4) return;
    float4 v = in[i];
    __nv_bfloat162 h01 = __floats2bfloat162_rn(v.x, v.y);
    __nv_bfloat162 h23 = __floats2bfloat162_rn(v.z, v.w);
    float lx = v.x - __bfloat162float(h01.x);
    float ly = v.y - __bfloat162float(h01.y);
    float lz = v.z - __bfloat162float(h23.x);
    float lw = v.w - __bfloat162float(h23.y);
    __nv_bfloat162 l01 = __floats2bfloat162_rn(lx, ly);
    __nv_bfloat162 l23 = __floats2bfloat162_rn(lz, lw);
    hi[2*i]   = h01;
    hi[2*i+1] = h23;
    lo[2*i]   = l01;
    lo[2*i+1] = l23;
}

// ---------------- fp32 tiled SGEMM (small GEMMs) ----------------
template<int BM, int BN, int BK, int TM, int TN, int EPI>
__global__ void __launch_bounds__((BM/TM)*(BN/TN))
sgemm_nt(const float* __restrict__ A, int lda,
         const float* __restrict__ Bm, int ldb,
         float* __restrict__ C, int ldc,
         int M, int N, int K, int kChunk,
         const float* __restrict__ bias)
{
    constexpr int THREADS = (BM/TM)*(BN/TN);
    constexpr int KQ = BK / 4;
    constexpr int A4 = BM * BK / 4;
    constexpr int B4 = BN * BK / 4;

    __shared__ float As[BK][BM];
    __shared__ float Bs[BK][BN];

    const int tid = threadIdx.x;
    const int n0  = blockIdx.x * BN;
    const int m0  = blockIdx.y * BM;
    const int kb  = blockIdx.z * kChunk;
    const int ke  = (kb + kChunk < K) ? (kb + kChunk) : K;

    const int tc = tid % (BN / TN);
    const int tr = tid / (BN / TN);

    float acc[TM][TN];
    #pragma unroll
    for (int i = 0; i < TM; i++)
        #pragma unroll
        for (int j = 0; j < TN; j++) acc[i][j] = 0.0f;

    for (int k0 = kb; k0 < ke; k0 += BK) {
        #pragma unroll
        for (int i = tid; i < A4; i += THREADS) {
            int m  = i / KQ;
            int kq = i % KQ;
            float4 v = *(const float4*)&A[(size_t)(m0 + m) * lda + k0 + kq * 4];
            As[kq*4+0][m] = v.x; As[kq*4+1][m] = v.y;
            As[kq*4+2][m] = v.z; As[kq*4+3][m] = v.w;
        }
        #pragma unroll
        for (int i = tid; i < B4; i += THREADS) {
            int n  = i / KQ;
            int kq = i % KQ;
            float4 v = *(const float4*)&Bm[(size_t)(n0 + n) * ldb + k0 + kq * 4];
            Bs[kq*4+0][n] = v.x; Bs[kq*4+1][n] = v.y;
            Bs[kq*4+2][n] = v.z; Bs[kq*4+3][n] = v.w;
        }
        __syncthreads();

        #pragma unroll
        for (int kk = 0; kk < BK; kk++) {
            float a[TM], b[TN];
            #pragma unroll
            for (int i = 0; i < TM; i++) a[i] = As[kk][tr*TM + i];
            #pragma unroll
            for (int j = 0; j < TN; j++) b[j] = Bs[kk][tc*TN + j];
            #pragma unroll
            for (int i = 0; i < TM; i++)
                #pragma unroll
                for (int j = 0; j < TN; j++)
                    acc[i][j] = fmaf(a[i], b[j], acc[i][j]);
        }
        __syncthreads();
    }

    #pragma unroll
    for (int i = 0; i < TM; i++) {
        int m = m0 + tr*TM + i;
        #pragma unroll
        for (int j = 0; j < TN; j++) {
            int n = n0 + tc*TN + j;
            float v = acc[i][j];
            if (EPI == 0) {
                C[(size_t)m * ldc + n] = v;
            } else if (EPI == 1) {
                atomicAdd(&C[(size_t)m * ldc + n], v);
            } else {
                float x = v + bias[n];
                float r2 = fmaxf(x, 0.0f) + log1pf(__expf(-fabsf(x)));
                C[(size_t)m * ldc + n] = r2;
            }
        }
    }
}

// ---------------- conv window shift + SiLU ----------------
__global__ void conv_kernel(const float* __restrict__ cs_in,
                            const float* __restrict__ conv_w,
                            const float* __restrict__ conv_b,
                            float* __restrict__ cs_out)
{
    int idx = blockIdx.x * blockDim.x + threadIdx.x;
    int b = idx >> 13;
    int d = idx & (DINNER - 1);
    float4 cs = ((const float4*)cs_in)[idx];
    float4 w  = ((const float4*)conv_w)[d];
    float xi  = g_xz[(size_t)b * (2*DINNER) + d];
    float s = cs.y*w.x + cs.z*w.y + cs.w*w.z + xi*w.w + conv_b[d];
    float sig = 1.0f / (1.0f + __expf(-s));
    g_xc[idx] = s * sig;
    ((float4*)cs_out)[idx] = make_float4(cs.y, cs.z, cs.w, xi);
}

// ---------------- SSM state update + y (emits y as bf16 hi/lo) --------------
__global__ void ssm_kernel(const float* __restrict__ ssm_in,
                           const float* __restrict__ D_param,
                           float* __restrict__ ssm_out)
{
    __shared__ float bm[DSTATE], cm[DSTATE];
    const int b = blockIdx.y;
    const int d = blockIdx.x * blockDim.x + threadIdx.x;
    if (threadIdx.x < 2*DSTATE) {
        float v = g_xdb[b * XPN + DTRANK + threadIdx.x];
        if (threadIdx.x < DSTATE) bm[threadIdx.x] = v;
        else                      cm[threadIdx.x - DSTATE] = v;
    }
    __syncthreads();

    const int bd = b * DINNER + d;
    const float dtv = g_dt[bd];
    const float xcv = g_xc[bd];
    const float xdt = xcv * dtv;
    const size_t base = (size_t)bd * DSTATE;

    float yacc = 0.0f;
    #pragma unroll
    for (int n = 0; n < DSTATE; n += 4) {
        float4 a  = *(const float4*)&g_A[d * DSTATE + n];
        float4 st = *(const float4*)&ssm_in[base + n];
        float4 ns;
        ns.x = st.x * __expf(a.x * dtv) + xdt * bm[n+0];
        ns.y = st.y * __expf(a.y * dtv) + xdt * bm[n+1];
        ns.z = st.z * __expf(a.z * dtv) + xdt * bm[n+2];
        ns.w = st.w * __expf(a.w * dtv) + xdt * bm[n+3];
        yacc += ns.x * cm[n+0] + ns.y * cm[n+1] + ns.z * cm[n+2] + ns.w * cm[n+3];
        *(float4*)&ssm_out[base + n] = ns;
    }
    yacc += D_param[d] * xcv;
    float zv = g_xz[(size_t)b * (2*DINNER) + DINNER + d];
    yacc *= zv / (1.0f + __expf(-zv));

    __nv_bfloat16 h = __float2bfloat16(yacc);
    g_yhi[bd] = h;
    g_ylo[bd] = __float2bfloat16(yacc - __bfloat162float(h));
}

// ---------------- launch ----------------
extern "C" void kernel_launch(void* const* d_in, const int* in_sizes, int n_in,
                              void* d_out, int out_size)
{
    const float* x       = (const float*)d_in[0];
    const float* cs_in   = (const float*)d_in[1];
    const float* ssm_in  = (const float*)d_in[2];
    const float* W_in    = (const float*)d_in[3];
    const float* conv_w  = (const float*)d_in[4];
    const float* conv_b  = (const float*)d_in[5];
    const float* W_xproj = (const float*)d_in[6];
    const float* W_dt    = (const float*)d_in[7];
    const float* b_dt    = (const float*)d_in[8];
    const float* A_log   = (const float*)d_in[9];
    const float* D_param = (const float*)d_in[10];
    const float* W_out   = (const float*)d_in[11];

    float* out     = (float*)d_out;
    float* cs_out  = out + (size_t)BB * DMODEL;
    float* ssm_out = cs_out + (size_t)BB * DINNER * 4;

    void *p_xz, *p_xc, *p_xdb, *p_dt;
    void *p_xhi, *p_xlo, *p_winhi, *p_winlo, *p_wouthi, *p_woutlo, *p_yhi, *p_ylo;
    cudaGetSymbolAddress(&p_xz,  g_xz);
    cudaGetSymbolAddress(&p_xc,  g_xc);
    cudaGetSymbolAddress(&p_xdb, g_xdb);
    cudaGetSymbolAddress(&p_dt,  g_dt);
    cudaGetSymbolAddress(&p_xhi, g_xhi);
    cudaGetSymbolAddress(&p_xlo, g_xlo);
    cudaGetSymbolAddress(&p_winhi, g_winhi);
    cudaGetSymbolAddress(&p_winlo, g_winlo);
    cudaGetSymbolAddress(&p_wouthi, g_wouthi);
    cudaGetSymbolAddress(&p_woutlo, g_woutlo);
    cudaGetSymbolAddress(&p_yhi, g_yhi);
    cudaGetSymbolAddress(&p_ylo, g_ylo);

    const int HSM = 2 * STG_BYTES;   // 81920 bytes
    cudaFuncSetAttribute(hmma_gemm<0,1>, cudaFuncAttributeMaxDynamicSharedMemorySize, HSM);
    cudaFuncSetAttribute(hmma_gemm<1,4>, cudaFuncAttributeMaxDynamicSharedMemorySize, HSM);

    // zero split-K accumulation targets
    zero_kernel<<<(BB*XPN + 255)/256, 256>>>((float*)p_xdb, BB*XPN);
    zero_kernel<<<(BB*DMODEL + 255)/256, 256>>>(out, BB*DMODEL);
    precompute_A_kernel<<<(DINNER*DSTATE + 255)/256, 256>>>(A_log);

    // pre-split x and W_in (needed by GEMM1)
    split_bf16_kernel<<<(BB*DMODEL/4 + 255)/256, 256>>>(
        (const float4*)x, (__nv_bfloat162*)p_xhi, (__nv_bfloat162*)p_xlo, BB*DMODEL/4);
    split_bf16_kernel<<<(2*DINNER*DMODEL/4 + 255)/256, 256>>>(
        (const float4*)W_in, (__nv_bfloat162*)p_winhi, (__nv_bfloat162*)p_winlo,
        2*DINNER*DMODEL/4);

    // GEMM1: xz[256,16384] = x @ W_in^T
    hmma_gemm<0,1><<<dim3((2*DINNER)/GBN, BB/GBM, 1), 256, HSM>>>(
        (const __nv_bfloat16*)p_xhi, (const __nv_bfloat16*)p_xlo,
        (const __nv_bfloat16*)p_winhi, (const __nv_bfloat16*)p_winlo,
        (float*)p_xz, 2*DINNER, DMODEL);

    // conv + SiLU
    conv_kernel<<<(BB*DINNER)/256, 256>>>(cs_in, conv_w, conv_b, cs_out);

    // GEMM3: x_db[256,160] = xc @ W_xproj^T  (fp32, BK=32, split-K=16, atomic)
    sgemm_nt<64,32,32,4,4,1><<<dim3(XPN/32, BB/64, 16), 128>>>(
        (const float*)p_xc, DINNER, W_xproj, DINNER, (float*)p_xdb, XPN,
        BB, XPN, DINNER, DINNER/16, nullptr);

    // GEMM4: dt[256,8192] = softplus(x_db[:, :128] @ W_dt^T + b_dt)  (fp32, BK=32)
    sgemm_nt<64,64,32,4,4,2><<<dim3(DINNER/64, BB/64, 1), 256>>>(
        (const float*)p_xdb, XPN, W_dt, DTRANK, (float*)p_dt, DINNER,
        BB, DINNER, DTRANK, DTRANK, b_dt);

    // pre-split W_out (no dependency on above; any order works on one stream)
    split_bf16_kernel<<<(DMODEL*DINNER/4 + 255)/256, 256>>>(
        (const float4*)W_out, (__nv_bfloat162*)p_wouthi, (__nv_bfloat162*)p_woutlo,
        DMODEL*DINNER/4);

    // SSM update + y (emits yhi/ylo)
    ssm_kernel<<<dim3(DINNER/256, BB), 256>>>(ssm_in, D_param, ssm_out);

    // GEMM6: out[256,2048] = y @ W_out^T  (split-K=4, atomic)
    hmma_gemm<1,4><<<dim3(DMODEL/GBN, BB/GBM, 4), 256, HSM>>>(
        (const __nv_bfloat16*)p_yhi, (const __nv_bfloat16*)p_ylo,
        (const __nv_bfloat16*)p_wouthi, (const __nv_bfloat16*)p_woutlo,
        out, DMODEL, DINNER);
}

// round 8
// speedup vs baseline: 1.0764x; 1.0118x over previous
#include <cuda_runtime.h>
#include <cuda_bf16.h>
#include <math.h>
#include <cstdint>

// ---------------- problem constants ----------------
#define BB       256
#define DMODEL   2048
#define DINNER   8192
#define DSTATE   16
#define DTRANK   128
#define XPN      (DTRANK + 2*DSTATE)   // 160

// ---------------- scratch (device globals; no allocation) ----------------
__device__ float g_xz [BB * 2 * DINNER];   // xi | z
__device__ float g_xc [BB * DINNER];
__device__ float g_xdb[BB * XPN];
__device__ float g_dt [BB * DINNER];
__device__ float g_A  [DINNER * DSTATE];

// bf16 hi/lo split tensors (pre-split in gmem)
__device__ __nv_bfloat16 g_xhi  [BB * DMODEL];
__device__ __nv_bfloat16 g_xlo  [BB * DMODEL];
__device__ __nv_bfloat16 g_winhi[2 * DINNER * DMODEL];
__device__ __nv_bfloat16 g_winlo[2 * DINNER * DMODEL];
__device__ __nv_bfloat16 g_wouthi[DMODEL * DINNER];
__device__ __nv_bfloat16 g_woutlo[DMODEL * DINNER];
__device__ __nv_bfloat16 g_yhi  [BB * DINNER];
__device__ __nv_bfloat16 g_ylo  [BB * DINNER];

// ---------------- helpers ----------------
__device__ __forceinline__ uint32_t smem_u32(const void* p) {
    uint32_t a;
    asm("{ .reg .u64 t; cvta.to.shared.u64 t, %1; cvt.u32.u64 %0, t; }" : "=r"(a) : "l"(p));
    return a;
}

__device__ __forceinline__ void ldmx4(uint32_t* r, uint32_t addr) {
    asm volatile("ldmatrix.sync.aligned.m8n8.x4.shared.b16 {%0,%1,%2,%3}, [%4];"
        : "=r"(r[0]), "=r"(r[1]), "=r"(r[2]), "=r"(r[3]) : "r"(addr));
}

__device__ __forceinline__ void mma16816(float* d, const uint32_t* a,
                                         uint32_t b0, uint32_t b1) {
    asm volatile(
        "mma.sync.aligned.m16n8k16.row.col.f32.bf16.bf16.f32 "
        "{%0,%1,%2,%3}, {%4,%5,%6,%7}, {%8,%9}, {%0,%1,%2,%3};"
        : "+f"(d[0]), "+f"(d[1]), "+f"(d[2]), "+f"(d[3])
        : "r"(a[0]), "r"(a[1]), "r"(a[2]), "r"(a[3]), "r"(b0), "r"(b1));
}

__device__ __forceinline__ void cp16(uint32_t s, const void* g) {
    asm volatile("cp.async.cg.shared.global [%0], [%1], 16;" :: "r"(s), "l"(g));
}
#define CP_COMMIT() asm volatile("cp.async.commit_group;" ::: "memory")
#define CP_WAIT(n)  asm volatile("cp.async.wait_group %0;" :: "n"(n) : "memory")

// ---------------- HMMA bf16 hi/lo GEMM (pre-split operands) ----------------
// C[M,N] (+)= (Ah+Al)[M,K] * (Bh+Bl)[N,K]^T, 3-product compensation.
// 256 threads, CTA tile 256x128x32, 8 warps 4m x 2n (warp tile 64x64).
// cp.async double-buffered. iters must be >= 2.
// EPI: 0 = store, 1 = atomicAdd (split-K)
#define GBM 256
#define GBN 128
#define GBK 32
#define GSK 40                           // padded bf16 row stride
#define AH_OFF 0
#define AL_OFF (GBM * GSK)               // 10240 elems
#define BH_OFF (2 * GBM * GSK)           // 20480
#define BL_OFF (BH_OFF + GBN * GSK)      // 25600
#define STG_ELEMS (2*GBM*GSK + 2*GBN*GSK)  // 30720
#define STG_BYTES (STG_ELEMS * 2)          // 61440

template<int EPI, int SPLITK>
__global__ void __launch_bounds__(256, 1)
hmma_gemm(const __nv_bfloat16* __restrict__ Ah, const __nv_bfloat16* __restrict__ Al,
          const __nv_bfloat16* __restrict__ Bh, const __nv_bfloat16* __restrict__ Bl,
          float* __restrict__ C, int ldc, int K)
{
    extern __shared__ __nv_bfloat16 sm[];

    const int tid = threadIdx.x;
    const int n0  = blockIdx.x * GBN;
    const int m0  = blockIdx.y * GBM;
    const int kChunk = K / SPLITK;
    const int kb  = blockIdx.z * kChunk;
    const int iters = kChunk / GBK;

    const uint32_t usm = smem_u32(sm);

    auto issue = [&](uint32_t sbase, int koff) {
        // A arrays: 1024 chunks (16B) each, 4 per thread
        #pragma unroll
        for (int u = 0; u < 4; u++) {
            int c   = u * 256 + tid;
            int row = c >> 2;
            int ch  = (c & 3) * 8;              // bf16 elems
            size_t ga = (size_t)(m0 + row) * K + koff + ch;
            uint32_t so = (uint32_t)(row * GSK + ch) * 2;
            cp16(sbase + AH_OFF*2 + so, Ah + ga);
            cp16(sbase + AL_OFF*2 + so, Al + ga);
        }
        // B arrays: 512 chunks each, 2 per thread
        #pragma unroll
        for (int u = 0; u < 2; u++) {
            int c   = u * 256 + tid;
            int row = c >> 2;
            int ch  = (c & 3) * 8;
            size_t gb = (size_t)(n0 + row) * K + koff + ch;
            uint32_t so = (uint32_t)(row * GSK + ch) * 2;
            cp16(sbase + BH_OFF*2 + so, Bh + gb);
            cp16(sbase + BL_OFF*2 + so, Bl + gb);
        }
    };

    issue(usm, kb);
    CP_COMMIT();
    issue(usm + STG_BYTES, kb + GBK);
    CP_COMMIT();

    // warp mapping: 4m x 2n, warp tile 64x64
    const int w    = tid >> 5;
    const int lane = tid & 31;
    const int wm   = (w & 3) * 64;
    const int wn   = (w >> 2) * 64;
    const int g    = lane >> 3;
    const int rr   = lane & 7;

    float acc[4][8][4];
    #pragma unroll
    for (int i = 0; i < 4; i++)
        #pragma unroll
        for (int j = 0; j < 8; j++)
            #pragma unroll
            for (int c = 0; c < 4; c++) acc[i][j][c] = 0.0f;

    for (int it = 0; it < iters; ++it) {
        const int s = it & 1;
        if (it + 1 < iters) { CP_WAIT(1); } else { CP_WAIT(0); }
        __syncthreads();

        const uint32_t uS  = usm + (uint32_t)s * STG_BYTES;
        const uint32_t uAh = uS + AH_OFF*2;
        const uint32_t uAl = uS + AL_OFF*2;
        const uint32_t uBh = uS + BH_OFF*2;
        const uint32_t uBl = uS + BL_OFF*2;

        #pragma unroll
        for (int ks = 0; ks < 2; ks++) {
            const int kcol = ks * 16 + (g >> 1) * 8;

            // load all A fragments for this ks (held live)
            uint32_t ah[4][4], al[4][4];
            #pragma unroll
            for (int mi = 0; mi < 4; mi++) {
                int arow = wm + mi * 16 + (g & 1) * 8 + rr;
                uint32_t off = (uint32_t)(arow * GSK + kcol) * 2;
                ldmx4(ah[mi], uAh + off);
                ldmx4(al[mi], uAl + off);
            }

            // stream B in 16-row (2-ni) groups
            #pragma unroll
            for (int pi = 0; pi < 4; pi++) {
                int brow = wn + pi * 16 + (g & 1) * 8 + rr;
                uint32_t off = (uint32_t)(brow * GSK + kcol) * 2;
                uint32_t th[4], tl[4];
                ldmx4(th, uBh + off);
                ldmx4(tl, uBl + off);
                #pragma unroll
                for (int mi = 0; mi < 4; mi++) {
                    mma16816(acc[mi][2*pi+0], ah[mi], th[0], th[2]);
                    mma16816(acc[mi][2*pi+0], al[mi], th[0], th[2]);
                    mma16816(acc[mi][2*pi+0], ah[mi], tl[0], tl[2]);
                    mma16816(acc[mi][2*pi+1], ah[mi], th[1], th[3]);
                    mma16816(acc[mi][2*pi+1], al[mi], th[1], th[3]);
                    mma16816(acc[mi][2*pi+1], ah[mi], tl[1], tl[3]);
                }
            }
        }
        __syncthreads();
        if (it + 2 < iters) {
            issue(usm + (uint32_t)s * STG_BYTES, kb + (it + 2) * GBK);
            CP_COMMIT();
        }
    }

    // ---- epilogue ----
    const int erow = lane >> 2;
    const int ecol = (lane & 3) * 2;
    #pragma unroll
    for (int mi = 0; mi < 4; mi++) {
        #pragma unroll
        for (int ni = 0; ni < 8; ni++) {
            int r0 = m0 + wm + mi * 16 + erow;
            int c0 = n0 + wn + ni * 8 + ecol;
            float* p0 = C + (size_t)r0 * ldc + c0;
            float* p1 = C + (size_t)(r0 + 8) * ldc + c0;
            if (EPI == 0) {
                *(float2*)p0 = make_float2(acc[mi][ni][0], acc[mi][ni][1]);
                *(float2*)p1 = make_float2(acc[mi][ni][2], acc[mi][ni][3]);
            } else {
                atomicAdd(p0,     acc[mi][ni][0]);
                atomicAdd(p0 + 1, acc[mi][ni][1]);
                atomicAdd(p1,     acc[mi][ni][2]);
                atomicAdd(p1 + 1, acc[mi][ni][3]);
            }
        }
    }
}

// ---------------- small helpers ----------------
__global__ void zero_kernel(float* __restrict__ p, int n) {
    int i = blockIdx.x * blockDim.x + threadIdx.x;
    if (i < n) p[i] = 0.0f;
}

__global__ void precompute_A_kernel(const float* __restrict__ A_log) {
    int i = blockIdx.x * blockDim.x + threadIdx.x;
    if (i < DINNER * DSTATE) g_A[i] = -expf(A_log[i]);
}

// split fp32 -> bf16 hi + bf16 lo (residual), float4-vectorized
__global__ void split_bf16_kernel(const float4* __restrict__ in,
                                  __nv_bfloat162* __restrict__ hi,
                                  __nv_bfloat162* __restrict__ lo, int n4) {
    int i = blockIdx.x * blockDim.x + threadIdx.x;
    if (i >= n4) return;
    float4 v = in[i];
    __nv_bfloat162 h01 = __floats2bfloat162_rn(v.x, v.y);
    __nv_bfloat162 h23 = __floats2bfloat162_rn(v.z, v.w);
    float lx = v.x - __bfloat162float(h01.x);
    float ly = v.y - __bfloat162float(h01.y);
    float lz = v.z - __bfloat162float(h23.x);
    float lw = v.w - __bfloat162float(h23.y);
    __nv_bfloat162 l01 = __floats2bfloat162_rn(lx, ly);
    __nv_bfloat162 l23 = __floats2bfloat162_rn(lz, lw);
    hi[2*i]   = h01;
    hi[2*i+1] = h23;
    lo[2*i]   = l01;
    lo[2*i+1] = l23;
}

// ---------------- fp32 tiled SGEMM (small GEMMs) ----------------
template<int BM, int BN, int BK, int TM, int TN, int EPI>
__global__ void __launch_bounds__((BM/TM)*(BN/TN))
sgemm_nt(const float* __restrict__ A, int lda,
         const float* __restrict__ Bm, int ldb,
         float* __restrict__ C, int ldc,
         int M, int N, int K, int kChunk,
         const float* __restrict__ bias)
{
    constexpr int THREADS = (BM/TM)*(BN/TN);
    constexpr int KQ = BK / 4;
    constexpr int A4 = BM * BK / 4;
    constexpr int B4 = BN * BK / 4;

    __shared__ float As[BK][BM];
    __shared__ float Bs[BK][BN];

    const int tid = threadIdx.x;
    const int n0  = blockIdx.x * BN;
    const int m0  = blockIdx.y * BM;
    const int kb  = blockIdx.z * kChunk;
    const int ke  = (kb + kChunk < K) ? (kb + kChunk) : K;

    const int tc = tid % (BN / TN);
    const int tr = tid / (BN / TN);

    float acc[TM][TN];
    #pragma unroll
    for (int i = 0; i < TM; i++)
        #pragma unroll
        for (int j = 0; j < TN; j++) acc[i][j] = 0.0f;

    for (int k0 = kb; k0 < ke; k0 += BK) {
        #pragma unroll
        for (int i = tid; i < A4; i += THREADS) {
            int m  = i / KQ;
            int kq = i % KQ;
            float4 v = *(const float4*)&A[(size_t)(m0 + m) * lda + k0 + kq * 4];
            As[kq*4+0][m] = v.x; As[kq*4+1][m] = v.y;
            As[kq*4+2][m] = v.z; As[kq*4+3][m] = v.w;
        }
        #pragma unroll
        for (int i = tid; i < B4; i += THREADS) {
            int n  = i / KQ;
            int kq = i % KQ;
            float4 v = *(const float4*)&Bm[(size_t)(n0 + n) * ldb + k0 + kq * 4];
            Bs[kq*4+0][n] = v.x; Bs[kq*4+1][n] = v.y;
            Bs[kq*4+2][n] = v.z; Bs[kq*4+3][n] = v.w;
        }
        __syncthreads();

        #pragma unroll
        for (int kk = 0; kk < BK; kk++) {
            float a[TM], b[TN];
            #pragma unroll
            for (int i = 0; i < TM; i++) a[i] = As[kk][tr*TM + i];
            #pragma unroll
            for (int j = 0; j < TN; j++) b[j] = Bs[kk][tc*TN + j];
            #pragma unroll
            for (int i = 0; i < TM; i++)
                #pragma unroll
                for (int j = 0; j < TN; j++)
                    acc[i][j] = fmaf(a[i], b[j], acc[i][j]);
        }
        __syncthreads();
    }

    #pragma unroll
    for (int i = 0; i < TM; i++) {
        int m = m0 + tr*TM + i;
        #pragma unroll
        for (int j = 0; j < TN; j++) {
            int n = n0 + tc*TN + j;
            float v = acc[i][j];
            if (EPI == 0) {
                C[(size_t)m * ldc + n] = v;
            } else if (EPI == 1) {
                atomicAdd(&C[(size_t)m * ldc + n], v);
            } else {
                float x = v + bias[n];
                float r2 = fmaxf(x, 0.0f) + log1pf(__expf(-fabsf(x)));
                C[(size_t)m * ldc + n] = r2;
            }
        }
    }
}

// ---------------- conv window shift + SiLU ----------------
__global__ void conv_kernel(const float* __restrict__ cs_in,
                            const float* __restrict__ conv_w,
                            const float* __restrict__ conv_b,
                            float* __restrict__ cs_out)
{
    int idx = blockIdx.x * blockDim.x + threadIdx.x;
    int b = idx >> 13;
    int d = idx & (DINNER - 1);
    float4 cs = ((const float4*)cs_in)[idx];
    float4 w  = ((const float4*)conv_w)[d];
    float xi  = g_xz[(size_t)b * (2*DINNER) + d];
    float s = cs.y*w.x + cs.z*w.y + cs.w*w.z + xi*w.w + conv_b[d];
    float sig = 1.0f / (1.0f + __expf(-s));
    g_xc[idx] = s * sig;
    ((float4*)cs_out)[idx] = make_float4(cs.y, cs.z, cs.w, xi);
}

// ---------------- SSM state update + y (emits y as bf16 hi/lo) --------------
__global__ void ssm_kernel(const float* __restrict__ ssm_in,
                           const float* __restrict__ D_param,
                           float* __restrict__ ssm_out)
{
    __shared__ float bm[DSTATE], cm[DSTATE];
    const int b = blockIdx.y;
    const int d = blockIdx.x * blockDim.x + threadIdx.x;
    if (threadIdx.x < 2*DSTATE) {
        float v = g_xdb[b * XPN + DTRANK + threadIdx.x];
        if (threadIdx.x < DSTATE) bm[threadIdx.x] = v;
        else                      cm[threadIdx.x - DSTATE] = v;
    }
    __syncthreads();

    const int bd = b * DINNER + d;
    const float dtv = g_dt[bd];
    const float xcv = g_xc[bd];
    const float xdt = xcv * dtv;
    const size_t base = (size_t)bd * DSTATE;

    float yacc = 0.0f;
    #pragma unroll
    for (int n = 0; n < DSTATE; n += 4) {
        float4 a  = *(const float4*)&g_A[d * DSTATE + n];
        float4 st = *(const float4*)&ssm_in[base + n];
        float4 ns;
        ns.x = st.x * __expf(a.x * dtv) + xdt * bm[n+0];
        ns.y = st.y * __expf(a.y * dtv) + xdt * bm[n+1];
        ns.z = st.z * __expf(a.z * dtv) + xdt * bm[n+2];
        ns.w = st.w * __expf(a.w * dtv) + xdt * bm[n+3];
        yacc += ns.x * cm[n+0] + ns.y * cm[n+1] + ns.z * cm[n+2] + ns.w * cm[n+3];
        *(float4*)&ssm_out[base + n] = ns;
    }
    yacc += D_param[d] * xcv;
    float zv = g_xz[(size_t)b * (2*DINNER) + DINNER + d];
    yacc *= zv / (1.0f + __expf(-zv));

    __nv_bfloat16 h = __float2bfloat16(yacc);
    g_yhi[bd] = h;
    g_ylo[bd] = __float2bfloat16(yacc - __bfloat162float(h));
}

// ---------------- launch ----------------
extern "C" void kernel_launch(void* const* d_in, const int* in_sizes, int n_in,
                              void* d_out, int out_size)
{
    const float* x       = (const float*)d_in[0];
    const float* cs_in   = (const float*)d_in[1];
    const float* ssm_in  = (const float*)d_in[2];
    const float* W_in    = (const float*)d_in[3];
    const float* conv_w  = (const float*)d_in[4];
    const float* conv_b  = (const float*)d_in[5];
    const float* W_xproj = (const float*)d_in[6];
    const float* W_dt    = (const float*)d_in[7];
    const float* b_dt    = (const float*)d_in[8];
    const float* A_log   = (const float*)d_in[9];
    const float* D_param = (const float*)d_in[10];
    const float* W_out   = (const float*)d_in[11];

    float* out     = (float*)d_out;
    float* cs_out  = out + (size_t)BB * DMODEL;
    float* ssm_out = cs_out + (size_t)BB * DINNER * 4;

    void *p_xz, *p_xc, *p_xdb, *p_dt;
    void *p_xhi, *p_xlo, *p_winhi, *p_winlo, *p_wouthi, *p_woutlo, *p_yhi, *p_ylo;
    cudaGetSymbolAddress(&p_xz,  g_xz);
    cudaGetSymbolAddress(&p_xc,  g_xc);
    cudaGetSymbolAddress(&p_xdb, g_xdb);
    cudaGetSymbolAddress(&p_dt,  g_dt);
    cudaGetSymbolAddress(&p_xhi, g_xhi);
    cudaGetSymbolAddress(&p_xlo, g_xlo);
    cudaGetSymbolAddress(&p_winhi, g_winhi);
    cudaGetSymbolAddress(&p_winlo, g_winlo);
    cudaGetSymbolAddress(&p_wouthi, g_wouthi);
    cudaGetSymbolAddress(&p_woutlo, g_woutlo);
    cudaGetSymbolAddress(&p_yhi, g_yhi);
    cudaGetSymbolAddress(&p_ylo, g_ylo);

    const int HSM = 2 * STG_BYTES;   // 122880 bytes
    cudaFuncSetAttribute(hmma_gemm<0,1>, cudaFuncAttributeMaxDynamicSharedMemorySize, HSM);
    cudaFuncSetAttribute(hmma_gemm<1,8>, cudaFuncAttributeMaxDynamicSharedMemorySize, HSM);

    // zero split-K accumulation targets
    zero_kernel<<<(BB*XPN + 255)/256, 256>>>((float*)p_xdb, BB*XPN);
    zero_kernel<<<(BB*DMODEL + 255)/256, 256>>>(out, BB*DMODEL);
    precompute_A_kernel<<<(DINNER*DSTATE + 255)/256, 256>>>(A_log);

    // pre-split x and W_in (needed by GEMM1)
    split_bf16_kernel<<<(BB*DMODEL/4 + 255)/256, 256>>>(
        (const float4*)x, (__nv_bfloat162*)p_xhi, (__nv_bfloat162*)p_xlo, BB*DMODEL/4);
    split_bf16_kernel<<<(2*DINNER*DMODEL/4 + 255)/256, 256>>>(
        (const float4*)W_in, (__nv_bfloat162*)p_winhi, (__nv_bfloat162*)p_winlo,
        2*DINNER*DMODEL/4);

    // GEMM1: xz[256,16384] = x @ W_in^T   (M=256 in one m-tile, 128 CTAs)
    hmma_gemm<0,1><<<dim3((2*DINNER)/GBN, BB/GBM, 1), 256, HSM>>>(
        (const __nv_bfloat16*)p_xhi, (const __nv_bfloat16*)p_xlo,
        (const __nv_bfloat16*)p_winhi, (const __nv_bfloat16*)p_winlo,
        (float*)p_xz, 2*DINNER, DMODEL);

    // conv + SiLU
    conv_kernel<<<(BB*DINNER)/256, 256>>>(cs_in, conv_w, conv_b, cs_out);

    // GEMM3: x_db[256,160] = xc @ W_xproj^T  (fp32, BK=32, split-K=16, atomic)
    sgemm_nt<64,32,32,4,4,1><<<dim3(XPN/32, BB/64, 16), 128>>>(
        (const float*)p_xc, DINNER, W_xproj, DINNER, (float*)p_xdb, XPN,
        BB, XPN, DINNER, DINNER/16, nullptr);

    // GEMM4: dt[256,8192] = softplus(x_db[:, :128] @ W_dt^T + b_dt)  (fp32, BK=32)
    sgemm_nt<64,64,32,4,4,2><<<dim3(DINNER/64, BB/64, 1), 256>>>(
        (const float*)p_xdb, XPN, W_dt, DTRANK, (float*)p_dt, DINNER,
        BB, DINNER, DTRANK, DTRANK, b_dt);

    // pre-split W_out
    split_bf16_kernel<<<(DMODEL*DINNER/4 + 255)/256, 256>>>(
        (const float4*)W_out, (__nv_bfloat162*)p_wouthi, (__nv_bfloat162*)p_woutlo,
        DMODEL*DINNER/4);

    // SSM update + y (emits yhi/ylo)
    ssm_kernel<<<dim3(DINNER/256, BB), 256>>>(ssm_in, D_param, ssm_out);

    // GEMM6: out[256,2048] = y @ W_out^T  (split-K=8 -> 128 CTAs, atomic)
    hmma_gemm<1,8><<<dim3(DMODEL/GBN, BB/GBM, 8), 256, HSM>>>(
        (const __nv_bfloat16*)p_yhi, (const __nv_bfloat16*)p_ylo,
        (const __nv_bfloat16*)p_wouthi, (const __nv_bfloat16*)p_woutlo,
        out, DMODEL, DINNER);
}

// round 9
// speedup vs baseline: 1.2641x; 1.1744x over previous
#include <cuda_runtime.h>
#include <cuda_bf16.h>
#include <math.h>
#include <cstdint>

// ---------------- problem constants ----------------
#define BB       256
#define DMODEL   2048
#define DINNER   8192
#define DSTATE   16
#define DTRANK   128
#define XPN      (DTRANK + 2*DSTATE)   // 160

// ---------------- scratch (device globals; no allocation) ----------------
__device__ float g_xz [BB * 2 * DINNER];   // xi | z
__device__ float g_xc [BB * DINNER];
__device__ float g_xdb[BB * XPN];
__device__ float g_dt [BB * DINNER];
__device__ float g_A  [DINNER * DSTATE];

// bf16 hi/lo split tensors (A-operands only; tiny)
__device__ __nv_bfloat16 g_xhi  [BB * DMODEL];
__device__ __nv_bfloat16 g_xlo  [BB * DMODEL];
__device__ __nv_bfloat16 g_yhi  [BB * DINNER];
__device__ __nv_bfloat16 g_ylo  [BB * DINNER];

// ---------------- helpers ----------------
__device__ __forceinline__ uint32_t smem_u32(const void* p) {
    uint32_t a;
    asm("{ .reg .u64 t; cvta.to.shared.u64 t, %1; cvt.u32.u64 %0, t; }" : "=r"(a) : "l"(p));
    return a;
}

__device__ __forceinline__ void ldmx4(uint32_t* r, uint32_t addr) {
    asm volatile("ldmatrix.sync.aligned.m8n8.x4.shared.b16 {%0,%1,%2,%3}, [%4];"
        : "=r"(r[0]), "=r"(r[1]), "=r"(r[2]), "=r"(r[3]) : "r"(addr));
}

__device__ __forceinline__ void mma16816(float* d, const uint32_t* a,
                                         uint32_t b0, uint32_t b1) {
    asm volatile(
        "mma.sync.aligned.m16n8k16.row.col.f32.bf16.bf16.f32 "
        "{%0,%1,%2,%3}, {%4,%5,%6,%7}, {%8,%9}, {%0,%1,%2,%3};"
        : "+f"(d[0]), "+f"(d[1]), "+f"(d[2]), "+f"(d[3])
        : "r"(a[0]), "r"(a[1]), "r"(a[2]), "r"(a[3]), "r"(b0), "r"(b1));
}

__device__ __forceinline__ void cp16(uint32_t s, const void* g) {
    asm volatile("cp.async.cg.shared.global [%0], [%1], 16;" :: "r"(s), "l"(g));
}
#define CP_COMMIT() asm volatile("cp.async.commit_group;" ::: "memory")
#define CP_WAIT(n)  asm volatile("cp.async.wait_group %0;" :: "n"(n) : "memory")

// fp32 pair -> bf16x2 hi + bf16x2 lo (residual)
__device__ __forceinline__ void cvt_pair(float2 v, uint32_t& hi, uint32_t& lo) {
    __nv_bfloat162 h = __floats2bfloat162_rn(v.x, v.y);
    float2 hf = __bfloat1622float2(h);
    __nv_bfloat162 l = __floats2bfloat162_rn(v.x - hf.x, v.y - hf.y);
    hi = *(uint32_t*)&h;
    lo = *(uint32_t*)&l;
}

// ---------------- HMMA bf16 hi/lo GEMM ----------------
// C[M,N] (+)= (Ah+Al)[M,K] * Bf[N,K]^T with Bf fp32 split to hi/lo in-register.
// 3-product compensation (AhBh + AlBh + AhBl).
// 256 threads, tile 128x128x32, cp.async double-buffered, 2 CTAs/SM target.
// A: pre-split bf16 hi/lo. B: raw fp32 (converted at fragment load).
// EPI: 0 = store, 1 = atomicAdd (split-K). iters must be >= 2.
#define GBM 128
#define GBN 128
#define GBK 32
#define GSK 40                             // bf16 elems per A row (padded)
#define BSKF 40                            // fp32 elems per B row (padded)
#define AH_B 0
#define AL_B (GBM * GSK * 2)               // 10240 B
#define BF_B (2 * GBM * GSK * 2)           // 20480 B
#define STG_BYTES (BF_B + GBN * BSKF * 4)  // 20480 + 20480 = 40960 B

template<int EPI, int SPLITK>
__global__ void __launch_bounds__(256, 2)
hmma_gemm(const __nv_bfloat16* __restrict__ Ah, const __nv_bfloat16* __restrict__ Al,
          const float* __restrict__ Bf,
          float* __restrict__ C, int ldc, int K)
{
    extern __shared__ char smraw[];
    float* smf = (float*)smraw;            // for typed smem loads of B

    const int tid = threadIdx.x;
    const int n0  = blockIdx.x * GBN;
    const int m0  = blockIdx.y * GBM;
    const int kChunk = K / SPLITK;
    const int kb  = blockIdx.z * kChunk;
    const int iters = kChunk / GBK;

    const uint32_t usm = smem_u32(smraw);

    auto issue = [&](uint32_t sbase, int koff) {
        // A hi/lo: 512 chunks each (128 rows x 4 x 8-bf16 chunks)
        #pragma unroll
        for (int u = 0; u < 2; u++) {
            int c   = u * 256 + tid;
            int row = c >> 2;
            int ch  = (c & 3) * 8;                 // bf16 elems
            size_t ga = (size_t)(m0 + row) * K + koff + ch;
            uint32_t so = (uint32_t)(row * GSK + ch) * 2;
            cp16(sbase + AH_B + so, Ah + ga);
            cp16(sbase + AL_B + so, Al + ga);
        }
        // B fp32: 1024 chunks (128 rows x 8 x 4-float chunks)
        #pragma unroll
        for (int u = 0; u < 4; u++) {
            int c   = u * 256 + tid;
            int row = c >> 3;
            int ch  = (c & 7) * 4;                 // fp32 elems
            size_t gb = (size_t)(n0 + row) * K + koff + ch;
            cp16(sbase + BF_B + (uint32_t)(row * BSKF + ch) * 4, Bf + gb);
        }
    };

    issue(usm, kb);
    CP_COMMIT();
    issue(usm + STG_BYTES, kb + GBK);
    CP_COMMIT();

    // warp mapping: 2m x 4n, warp tile 64x32 (proven)
    const int w    = tid >> 5;
    const int lane = tid & 31;
    const int wm   = (w & 1) * 64;
    const int wn   = (w >> 1) * 32;
    const int g    = lane >> 3;
    const int rr   = lane & 7;
    const int bn   = lane >> 2;       // n within 8-tile for B conversion
    const int bk   = (lane & 3) * 2;  // k pair base within 16

    float acc[4][4][4];
    #pragma unroll
    for (int i = 0; i < 4; i++)
        #pragma unroll
        for (int j = 0; j < 4; j++)
            #pragma unroll
            for (int c = 0; c < 4; c++) acc[i][j][c] = 0.0f;

    for (int it = 0; it < iters; ++it) {
        const int s = it & 1;
        if (it + 1 < iters) { CP_WAIT(1); } else { CP_WAIT(0); }
        __syncthreads();

        const uint32_t uS  = usm + (uint32_t)s * STG_BYTES;
        const uint32_t uAh = uS + AH_B;
        const uint32_t uAl = uS + AL_B;
        const float*   sB  = smf + ((uint32_t)s * STG_BYTES + BF_B) / 4;

        #pragma unroll
        for (int ks = 0; ks < 2; ks++) {
            const int kcol = ks * 16 + (g >> 1) * 8;   // for ldmatrix (A)
            const int kbse = ks * 16 + bk;             // for B conversion

            // ---- B fragments from fp32 smem (hi/lo built in registers) ----
            uint32_t bh[4][2], bl[4][2];
            #pragma unroll
            for (int ni = 0; ni < 4; ni++) {
                const float* bp = sB + (wn + ni * 8 + bn) * BSKF + kbse;
                float2 p0 = *(const float2*)bp;
                float2 p1 = *(const float2*)(bp + 8);
                cvt_pair(p0, bh[ni][0], bl[ni][0]);
                cvt_pair(p1, bh[ni][1], bl[ni][1]);
            }
            // ---- A fragments (ldmatrix) + MMAs ----
            #pragma unroll
            for (int mi = 0; mi < 4; mi++) {
                int arow = wm + mi * 16 + (g & 1) * 8 + rr;
                uint32_t off = (uint32_t)(arow * GSK + kcol) * 2;
                uint32_t ah[4], al[4];
                ldmx4(ah, uAh + off);
                ldmx4(al, uAl + off);
                #pragma unroll
                for (int ni = 0; ni < 4; ni++) {
                    mma16816(acc[mi][ni], ah, bh[ni][0], bh[ni][1]);
                    mma16816(acc[mi][ni], al, bh[ni][0], bh[ni][1]);
                    mma16816(acc[mi][ni], ah, bl[ni][0], bl[ni][1]);
                }
            }
        }
        __syncthreads();
        if (it + 2 < iters) {
            issue(usm + (uint32_t)s * STG_BYTES, kb + (it + 2) * GBK);
            CP_COMMIT();
        }
    }

    // ---- epilogue ----
    const int erow = lane >> 2;
    const int ecol = (lane & 3) * 2;
    #pragma unroll
    for (int mi = 0; mi < 4; mi++) {
        #pragma unroll
        for (int ni = 0; ni < 4; ni++) {
            int r0 = m0 + wm + mi * 16 + erow;
            int c0 = n0 + wn + ni * 8 + ecol;
            float* p0 = C + (size_t)r0 * ldc + c0;
            float* p1 = C + (size_t)(r0 + 8) * ldc + c0;
            if (EPI == 0) {
                *(float2*)p0 = make_float2(acc[mi][ni][0], acc[mi][ni][1]);
                *(float2*)p1 = make_float2(acc[mi][ni][2], acc[mi][ni][3]);
            } else {
                atomicAdd(p0,     acc[mi][ni][0]);
                atomicAdd(p0 + 1, acc[mi][ni][1]);
                atomicAdd(p1,     acc[mi][ni][2]);
                atomicAdd(p1 + 1, acc[mi][ni][3]);
            }
        }
    }
}

// ---------------- small helpers ----------------
__global__ void zero_kernel(float* __restrict__ p, int n) {
    int i = blockIdx.x * blockDim.x + threadIdx.x;
    if (i < n) p[i] = 0.0f;
}

__global__ void precompute_A_kernel(const float* __restrict__ A_log) {
    int i = blockIdx.x * blockDim.x + threadIdx.x;
    if (i < DINNER * DSTATE) g_A[i] = -expf(A_log[i]);
}

// split fp32 -> bf16 hi + bf16 lo (residual), float4-vectorized (A operands only)
__global__ void split_bf16_kernel(const float4* __restrict__ in,
                                  __nv_bfloat162* __restrict__ hi,
                                  __nv_bfloat162* __restrict__ lo, int n4) {
    int i = blockIdx.x * blockDim.x + threadIdx.x;
    if (i >= n4) return;
    float4 v = in[i];
    __nv_bfloat162 h01 = __floats2bfloat162_rn(v.x, v.y);
    __nv_bfloat162 h23 = __floats2bfloat162_rn(v.z, v.w);
    float lx = v.x - __bfloat162float(h01.x);
    float ly = v.y - __bfloat162float(h01.y);
    float lz = v.z - __bfloat162float(h23.x);
    float lw = v.w - __bfloat162float(h23.y);
    hi[2*i]   = h01;
    hi[2*i+1] = h23;
    lo[2*i]   = __floats2bfloat162_rn(lx, ly);
    lo[2*i+1] = __floats2bfloat162_rn(lz, lw);
}

// ---------------- fp32 tiled SGEMM (small GEMMs) ----------------
template<int BM, int BN, int BK, int TM, int TN, int EPI>
__global__ void __launch_bounds__((BM/TM)*(BN/TN))
sgemm_nt(const float* __restrict__ A, int lda,
         const float* __restrict__ Bm, int ldb,
         float* __restrict__ C, int ldc,
         int M, int N, int K, int kChunk,
         const float* __restrict__ bias)
{
    constexpr int THREADS = (BM/TM)*(BN/TN);
    constexpr int KQ = BK / 4;
    constexpr int A4 = BM * BK / 4;
    constexpr int B4 = BN * BK / 4;

    __shared__ float As[BK][BM];
    __shared__ float Bs[BK][BN];

    const int tid = threadIdx.x;
    const int n0  = blockIdx.x * BN;
    const int m0  = blockIdx.y * BM;
    const int kb  = blockIdx.z * kChunk;
    const int ke  = (kb + kChunk < K) ? (kb + kChunk) : K;

    const int tc = tid % (BN / TN);
    const int tr = tid / (BN / TN);

    float acc[TM][TN];
    #pragma unroll
    for (int i = 0; i < TM; i++)
        #pragma unroll
        for (int j = 0; j < TN; j++) acc[i][j] = 0.0f;

    for (int k0 = kb; k0 < ke; k0 += BK) {
        #pragma unroll
        for (int i = tid; i < A4; i += THREADS) {
            int m  = i / KQ;
            int kq = i % KQ;
            float4 v = *(const float4*)&A[(size_t)(m0 + m) * lda + k0 + kq * 4];
            As[kq*4+0][m] = v.x; As[kq*4+1][m] = v.y;
            As[kq*4+2][m] = v.z; As[kq*4+3][m] = v.w;
        }
        #pragma unroll
        for (int i = tid; i < B4; i += THREADS) {
            int n  = i / KQ;
            int kq = i % KQ;
            float4 v = *(const float4*)&Bm[(size_t)(n0 + n) * ldb + k0 + kq * 4];
            Bs[kq*4+0][n] = v.x; Bs[kq*4+1][n] = v.y;
            Bs[kq*4+2][n] = v.z; Bs[kq*4+3][n] = v.w;
        }
        __syncthreads();

        #pragma unroll
        for (int kk = 0; kk < BK; kk++) {
            float a[TM], b[TN];
            #pragma unroll
            for (int i = 0; i < TM; i++) a[i] = As[kk][tr*TM + i];
            #pragma unroll
            for (int j = 0; j < TN; j++) b[j] = Bs[kk][tc*TN + j];
            #pragma unroll
            for (int i = 0; i < TM; i++)
                #pragma unroll
                for (int j = 0; j < TN; j++)
                    acc[i][j] = fmaf(a[i], b[j], acc[i][j]);
        }
        __syncthreads();
    }

    #pragma unroll
    for (int i = 0; i < TM; i++) {
        int m = m0 + tr*TM + i;
        #pragma unroll
        for (int j = 0; j < TN; j++) {
            int n = n0 + tc*TN + j;
            float v = acc[i][j];
            if (EPI == 0) {
                C[(size_t)m * ldc + n] = v;
            } else if (EPI == 1) {
                atomicAdd(&C[(size_t)m * ldc + n], v);
            } else {
                float x = v + bias[n];
                float r2 = fmaxf(x, 0.0f) + log1pf(__expf(-fabsf(x)));
                C[(size_t)m * ldc + n] = r2;
            }
        }
    }
}

// ---------------- conv window shift + SiLU ----------------
__global__ void conv_kernel(const float* __restrict__ cs_in,
                            const float* __restrict__ conv_w,
                            const float* __restrict__ conv_b,
                            float* __restrict__ cs_out)
{
    int idx = blockIdx.x * blockDim.x + threadIdx.x;
    int b = idx >> 13;
    int d = idx & (DINNER - 1);
    float4 cs = ((const float4*)cs_in)[idx];
    float4 w  = ((const float4*)conv_w)[d];
    float xi  = g_xz[(size_t)b * (2*DINNER) + d];
    float s = cs.y*w.x + cs.z*w.y + cs.w*w.z + xi*w.w + conv_b[d];
    float sig = 1.0f / (1.0f + __expf(-s));
    g_xc[idx] = s * sig;
    ((float4*)cs_out)[idx] = make_float4(cs.y, cs.z, cs.w, xi);
}

// ---------------- SSM state update + y (emits y as bf16 hi/lo) --------------
__global__ void ssm_kernel(const float* __restrict__ ssm_in,
                           const float* __restrict__ D_param,
                           float* __restrict__ ssm_out)
{
    __shared__ float bm[DSTATE], cm[DSTATE];
    const int b = blockIdx.y;
    const int d = blockIdx.x * blockDim.x + threadIdx.x;
    if (threadIdx.x < 2*DSTATE) {
        float v = g_xdb[b * XPN + DTRANK + threadIdx.x];
        if (threadIdx.x < DSTATE) bm[threadIdx.x] = v;
        else                      cm[threadIdx.x - DSTATE] = v;
    }
    __syncthreads();

    const int bd = b * DINNER + d;
    const float dtv = g_dt[bd];
    const float xcv = g_xc[bd];
    const float xdt = xcv * dtv;
    const size_t base = (size_t)bd * DSTATE;

    float yacc = 0.0f;
    #pragma unroll
    for (int n = 0; n < DSTATE; n += 4) {
        float4 a  = *(const float4*)&g_A[d * DSTATE + n];
        float4 st = *(const float4*)&ssm_in[base + n];
        float4 ns;
        ns.x = st.x * __expf(a.x * dtv) + xdt * bm[n+0];
        ns.y = st.y * __expf(a.y * dtv) + xdt * bm[n+1];
        ns.z = st.z * __expf(a.z * dtv) + xdt * bm[n+2];
        ns.w = st.w * __expf(a.w * dtv) + xdt * bm[n+3];
        yacc += ns.x * cm[n+0] + ns.y * cm[n+1] + ns.z * cm[n+2] + ns.w * cm[n+3];
        *(float4*)&ssm_out[base + n] = ns;
    }
    yacc += D_param[d] * xcv;
    float zv = g_xz[(size_t)b * (2*DINNER) + DINNER + d];
    yacc *= zv / (1.0f + __expf(-zv));

    __nv_bfloat16 h = __float2bfloat16(yacc);
    g_yhi[bd] = h;
    g_ylo[bd] = __float2bfloat16(yacc - __bfloat162float(h));
}

// ---------------- launch ----------------
extern "C" void kernel_launch(void* const* d_in, const int* in_sizes, int n_in,
                              void* d_out, int out_size)
{
    const float* x       = (const float*)d_in[0];
    const float* cs_in   = (const float*)d_in[1];
    const float* ssm_in  = (const float*)d_in[2];
    const float* W_in    = (const float*)d_in[3];
    const float* conv_w  = (const float*)d_in[4];
    const float* conv_b  = (const float*)d_in[5];
    const float* W_xproj = (const float*)d_in[6];
    const float* W_dt    = (const float*)d_in[7];
    const float* b_dt    = (const float*)d_in[8];
    const float* A_log   = (const float*)d_in[9];
    const float* D_param = (const float*)d_in[10];
    const float* W_out   = (const float*)d_in[11];

    float* out     = (float*)d_out;
    float* cs_out  = out + (size_t)BB * DMODEL;
    float* ssm_out = cs_out + (size_t)BB * DINNER * 4;

    void *p_xz, *p_xc, *p_xdb, *p_dt, *p_xhi, *p_xlo, *p_yhi, *p_ylo;
    cudaGetSymbolAddress(&p_xz,  g_xz);
    cudaGetSymbolAddress(&p_xc,  g_xc);
    cudaGetSymbolAddress(&p_xdb, g_xdb);
    cudaGetSymbolAddress(&p_dt,  g_dt);
    cudaGetSymbolAddress(&p_xhi, g_xhi);
    cudaGetSymbolAddress(&p_xlo, g_xlo);
    cudaGetSymbolAddress(&p_yhi, g_yhi);
    cudaGetSymbolAddress(&p_ylo, g_ylo);

    const int HSM = 2 * STG_BYTES;   // 81920 bytes -> 2 CTAs/SM
    cudaFuncSetAttribute(hmma_gemm<0,1>, cudaFuncAttributeMaxDynamicSharedMemorySize, HSM);
    cudaFuncSetAttribute(hmma_gemm<1,8>, cudaFuncAttributeMaxDynamicSharedMemorySize, HSM);

    // zero split-K accumulation targets
    zero_kernel<<<(BB*XPN + 255)/256, 256>>>((float*)p_xdb, BB*XPN);
    zero_kernel<<<(BB*DMODEL + 255)/256, 256>>>(out, BB*DMODEL);
    precompute_A_kernel<<<(DINNER*DSTATE + 255)/256, 256>>>(A_log);

    // pre-split x only (4 MB; W stays fp32 and is converted inside the GEMM)
    split_bf16_kernel<<<(BB*DMODEL/4 + 255)/256, 256>>>(
        (const float4*)x, (__nv_bfloat162*)p_xhi, (__nv_bfloat162*)p_xlo, BB*DMODEL/4);

    // GEMM1: xz[256,16384] = x @ W_in^T   (B = W_in fp32 direct)
    hmma_gemm<0,1><<<dim3((2*DINNER)/GBN, BB/GBM, 1), 256, HSM>>>(
        (const __nv_bfloat16*)p_xhi, (const __nv_bfloat16*)p_xlo,
        W_in, (float*)p_xz, 2*DINNER, DMODEL);

    // conv + SiLU
    conv_kernel<<<(BB*DINNER)/256, 256>>>(cs_in, conv_w, conv_b, cs_out);

    // GEMM3: x_db[256,160] = xc @ W_xproj^T  (fp32, BK=32, split-K=16, atomic)
    sgemm_nt<64,32,32,4,4,1><<<dim3(XPN/32, BB/64, 16), 128>>>(
        (const float*)p_xc, DINNER, W_xproj, DINNER, (float*)p_xdb, XPN,
        BB, XPN, DINNER, DINNER/16, nullptr);

    // GEMM4: dt[256,8192] = softplus(x_db[:, :128] @ W_dt^T + b_dt)  (fp32, BK=32)
    sgemm_nt<64,64,32,4,4,2><<<dim3(DINNER/64, BB/64, 1), 256>>>(
        (const float*)p_xdb, XPN, W_dt, DTRANK, (float*)p_dt, DINNER,
        BB, DINNER, DTRANK, DTRANK, b_dt);

    // SSM update + y (emits yhi/ylo)
    ssm_kernel<<<dim3(DINNER/256, BB), 256>>>(ssm_in, D_param, ssm_out);

    // GEMM6: out[256,2048] = y @ W_out^T  (B = W_out fp32 direct, split-K=8, atomic)
    hmma_gemm<1,8><<<dim3(DMODEL/GBN, BB/GBM, 8), 256, HSM>>>(
        (const __nv_bfloat16*)p_yhi, (const __nv_bfloat16*)p_ylo,
        W_out, out, DMODEL, DINNER);
}

// round 10
// speedup vs baseline: 1.3556x; 1.0724x over previous
#include <cuda_runtime.h>
#include <cuda_bf16.h>
#include <math.h>
#include <cstdint>

// ---------------- problem constants ----------------
#define BB       256
#define DMODEL   2048
#define DINNER   8192
#define DSTATE   16
#define DTRANK   128
#define XPN      (DTRANK + 2*DSTATE)   // 160

// ---------------- scratch (device globals; no allocation) ----------------
__device__ float g_xz [BB * 2 * DINNER];   // xi | z
__device__ float g_xc [BB * DINNER];
__device__ float g_xdb[BB * XPN];
__device__ float g_dt [BB * DINNER];
__device__ float g_A  [DINNER * DSTATE];

// bf16 hi/lo split tensors (A-operands only; tiny)
__device__ __nv_bfloat16 g_xhi  [BB * DMODEL];
__device__ __nv_bfloat16 g_xlo  [BB * DMODEL];
__device__ __nv_bfloat16 g_yhi  [BB * DINNER];
__device__ __nv_bfloat16 g_ylo  [BB * DINNER];

// ---------------- helpers ----------------
__device__ __forceinline__ uint32_t smem_u32(const void* p) {
    uint32_t a;
    asm("{ .reg .u64 t; cvta.to.shared.u64 t, %1; cvt.u32.u64 %0, t; }" : "=r"(a) : "l"(p));
    return a;
}

__device__ __forceinline__ void ldmx4(uint32_t* r, uint32_t addr) {
    asm volatile("ldmatrix.sync.aligned.m8n8.x4.shared.b16 {%0,%1,%2,%3}, [%4];"
        : "=r"(r[0]), "=r"(r[1]), "=r"(r[2]), "=r"(r[3]) : "r"(addr));
}

__device__ __forceinline__ void mma16816(float* d, const uint32_t* a,
                                         uint32_t b0, uint32_t b1) {
    asm volatile(
        "mma.sync.aligned.m16n8k16.row.col.f32.bf16.bf16.f32 "
        "{%0,%1,%2,%3}, {%4,%5,%6,%7}, {%8,%9}, {%0,%1,%2,%3};"
        : "+f"(d[0]), "+f"(d[1]), "+f"(d[2]), "+f"(d[3])
        : "r"(a[0]), "r"(a[1]), "r"(a[2]), "r"(a[3]), "r"(b0), "r"(b1));
}

__device__ __forceinline__ void cp16(uint32_t s, const void* g) {
    asm volatile("cp.async.cg.shared.global [%0], [%1], 16;" :: "r"(s), "l"(g));
}
#define CP_COMMIT() asm volatile("cp.async.commit_group;" ::: "memory")
#define CP_WAIT(n)  asm volatile("cp.async.wait_group %0;" :: "n"(n) : "memory")

// fp32 pair -> bf16x2 hi (truncation via PRMT) + bf16x2 lo (residual, RN)
__device__ __forceinline__ void cvt_pair(float2 v, uint32_t& hi, uint32_t& lo) {
    uint32_t ax = __float_as_uint(v.x), ay = __float_as_uint(v.y);
    uint32_t h;
    asm("prmt.b32 %0, %1, %2, 0x7632;" : "=r"(h) : "r"(ax), "r"(ay));
    float hx = __uint_as_float(ax & 0xFFFF0000u);
    float hy = __uint_as_float(ay & 0xFFFF0000u);
    __nv_bfloat162 l = __floats2bfloat162_rn(v.x - hx, v.y - hy);
    hi = h;
    lo = *(uint32_t*)&l;
}

// ---------------- HMMA bf16 hi/lo GEMM ----------------
// C[M,N] (+)= (Ah+Al)[M,K] * Bf[N,K]^T with Bf fp32 split to hi/lo in-register.
// 3-product compensation (AhBh + AlBh + AhBl).
// 256 threads, tile 128x128x32, 3-stage cp.async, swizzled compact smem
// (stage 32 KB -> 3 stages = 96 KB -> 2 CTAs/SM).
// A layout: 64 B rows, chunk swizzle c^((r>>1)&3)  (conflict-free ldmatrix)
// B layout: 128 B rows fp32, chunk swizzle c^(r&7)
// EPI: 0 = store, 1 = atomicAdd (split-K). iters must be >= 3.
#define GBM 128
#define GBN 128
#define GBK 32
#define AH_B 0
#define AL_B 8192
#define BF_B 16384
#define STG_BYTES 32768
#define NSTAGE 3

template<int EPI, int SPLITK>
__global__ void __launch_bounds__(256, 2)
hmma_gemm(const __nv_bfloat16* __restrict__ Ah, const __nv_bfloat16* __restrict__ Al,
          const float* __restrict__ Bf,
          float* __restrict__ C, int ldc, int K)
{
    extern __shared__ char smraw[];
    const float* smf = (const float*)smraw;

    const int tid = threadIdx.x;
    const int n0  = blockIdx.x * GBN;
    const int m0  = blockIdx.y * GBM;
    const int kChunk = K / SPLITK;
    const int kb  = blockIdx.z * kChunk;
    const int iters = kChunk / GBK;

    const uint32_t usm = smem_u32(smraw);

    auto issue = [&](uint32_t sbase, int koff) {
        // A hi/lo: 512 chunks each (128 rows x 4 x 8-bf16 chunks), 2 per thread
        #pragma unroll
        for (int u = 0; u < 2; u++) {
            int idx = u * 256 + tid;
            int r   = idx >> 2;
            int c   = idx & 3;
            size_t ga   = (size_t)(m0 + r) * K + koff + c * 8;
            uint32_t so = (uint32_t)(r * 64 + ((c ^ ((r >> 1) & 3)) * 16));
            cp16(sbase + AH_B + so, Ah + ga);
            cp16(sbase + AL_B + so, Al + ga);
        }
        // B fp32: 1024 chunks (128 rows x 8 x 4-float chunks), 4 per thread
        #pragma unroll
        for (int u = 0; u < 4; u++) {
            int idx = u * 256 + tid;
            int r   = idx >> 3;
            int c   = idx & 7;
            size_t gb   = (size_t)(n0 + r) * K + koff + c * 4;
            uint32_t so = (uint32_t)(r * 128 + ((c ^ (r & 7)) * 16));
            cp16(sbase + BF_B + so, Bf + gb);
        }
    };

    issue(usm, kb);                          CP_COMMIT();
    issue(usm + STG_BYTES, kb + GBK);        CP_COMMIT();
    issue(usm + 2 * STG_BYTES, kb + 2*GBK);  CP_COMMIT();

    // warp mapping: 2m x 4n, warp tile 64x32
    const int w    = tid >> 5;
    const int lane = tid & 31;
    const int wm   = (w & 1) * 64;
    const int wn   = (w >> 1) * 32;
    const int g    = lane >> 3;
    const int rr   = lane & 7;
    const int bn   = lane >> 2;       // n-row within 8-tile for B conversion
    const int bk   = (lane & 3) * 2;  // k pair base within 16

    float acc[4][4][4];
    #pragma unroll
    for (int i = 0; i < 4; i++)
        #pragma unroll
        for (int j = 0; j < 4; j++)
            #pragma unroll
            for (int c = 0; c < 4; c++) acc[i][j][c] = 0.0f;

    int s = 0;
    for (int it = 0; it < iters; ++it) {
        CP_WAIT(2);
        __syncthreads();

        const uint32_t uS  = usm + (uint32_t)s * STG_BYTES;
        const uint32_t uAh = uS + AH_B;
        const uint32_t uAl = uS + AL_B;
        const float*   sB  = smf + ((uint32_t)s * STG_BYTES + BF_B) / 4;

        #pragma unroll
        for (int ks = 0; ks < 2; ks++) {
            const int cA   = ks * 2 + (g >> 1);       // A chunk (8 bf16 = 16B)
            const int f0   = ks * 16 + bk;            // B float index (p0)

            // ---- B fragments from fp32 smem (hi/lo built in registers) ----
            uint32_t bh[4][2], bl[4][2];
            #pragma unroll
            for (int ni = 0; ni < 4; ni++) {
                int rB = wn + ni * 8 + bn;
                int c0 = f0 >> 2;
                int c1 = c0 + 2;
                const float* p0p = sB + rB * 32 + ((c0 ^ (rB & 7)) << 2) + (f0 & 3);
                const float* p1p = sB + rB * 32 + ((c1 ^ (rB & 7)) << 2) + (f0 & 3);
                float2 p0 = *(const float2*)p0p;
                float2 p1 = *(const float2*)p1p;
                cvt_pair(p0, bh[ni][0], bl[ni][0]);
                cvt_pair(p1, bh[ni][1], bl[ni][1]);
            }
            // ---- A fragments (ldmatrix, swizzled) + MMAs ----
            #pragma unroll
            for (int mi = 0; mi < 4; mi++) {
                int arow = wm + mi * 16 + (g & 1) * 8 + rr;
                uint32_t off = (uint32_t)(arow * 64 + ((cA ^ ((arow >> 1) & 3)) * 16));
                uint32_t ah[4], al[4];
                ldmx4(ah, uAh + off);
                ldmx4(al, uAl + off);
                #pragma unroll
                for (int ni = 0; ni < 4; ni++) {
                    mma16816(acc[mi][ni], ah, bh[ni][0], bh[ni][1]);
                    mma16816(acc[mi][ni], al, bh[ni][0], bh[ni][1]);
                    mma16816(acc[mi][ni], ah, bl[ni][0], bl[ni][1]);
                }
            }
        }
        __syncthreads();
        if (it + NSTAGE < iters)
            issue(usm + (uint32_t)s * STG_BYTES, kb + (it + NSTAGE) * GBK);
        CP_COMMIT();
        s = (s == NSTAGE - 1) ? 0 : s + 1;
    }

    // ---- epilogue ----
    const int erow = lane >> 2;
    const int ecol = (lane & 3) * 2;
    #pragma unroll
    for (int mi = 0; mi < 4; mi++) {
        #pragma unroll
        for (int ni = 0; ni < 4; ni++) {
            int r0 = m0 + wm + mi * 16 + erow;
            int c0 = n0 + wn + ni * 8 + ecol;
            float* p0 = C + (size_t)r0 * ldc + c0;
            float* p1 = C + (size_t)(r0 + 8) * ldc + c0;
            if (EPI == 0) {
                *(float2*)p0 = make_float2(acc[mi][ni][0], acc[mi][ni][1]);
                *(float2*)p1 = make_float2(acc[mi][ni][2], acc[mi][ni][3]);
            } else {
                atomicAdd(p0,     acc[mi][ni][0]);
                atomicAdd(p0 + 1, acc[mi][ni][1]);
                atomicAdd(p1,     acc[mi][ni][2]);
                atomicAdd(p1 + 1, acc[mi][ni][3]);
            }
        }
    }
}

// ---------------- small helpers ----------------
__global__ void zero_kernel(float* __restrict__ p, int n) {
    int i = blockIdx.x * blockDim.x + threadIdx.x;
    if (i < n) p[i] = 0.0f;
}

__global__ void precompute_A_kernel(const float* __restrict__ A_log) {
    int i = blockIdx.x * blockDim.x + threadIdx.x;
    if (i < DINNER * DSTATE) g_A[i] = -expf(A_log[i]);
}

// split fp32 -> bf16 hi + bf16 lo (residual), float4-vectorized (A operands only)
__global__ void split_bf16_kernel(const float4* __restrict__ in,
                                  __nv_bfloat162* __restrict__ hi,
                                  __nv_bfloat162* __restrict__ lo, int n4) {
    int i = blockIdx.x * blockDim.x + threadIdx.x;
    if (i >= n4) return;
    float4 v = in[i];
    __nv_bfloat162 h01 = __floats2bfloat162_rn(v.x, v.y);
    __nv_bfloat162 h23 = __floats2bfloat162_rn(v.z, v.w);
    float lx = v.x - __bfloat162float(h01.x);
    float ly = v.y - __bfloat162float(h01.y);
    float lz = v.z - __bfloat162float(h23.x);
    float lw = v.w - __bfloat162float(h23.y);
    hi[2*i]   = h01;
    hi[2*i+1] = h23;
    lo[2*i]   = __floats2bfloat162_rn(lx, ly);
    lo[2*i+1] = __floats2bfloat162_rn(lz, lw);
}

// ---------------- fp32 tiled SGEMM (small GEMMs) ----------------
template<int BM, int BN, int BK, int TM, int TN, int EPI>
__global__ void __launch_bounds__((BM/TM)*(BN/TN))
sgemm_nt(const float* __restrict__ A, int lda,
         const float* __restrict__ Bm, int ldb,
         float* __restrict__ C, int ldc,
         int M, int N, int K, int kChunk,
         const float* __restrict__ bias)
{
    constexpr int THREADS = (BM/TM)*(BN/TN);
    constexpr int KQ = BK / 4;
    constexpr int A4 = BM * BK / 4;
    constexpr int B4 = BN * BK / 4;

    __shared__ float As[BK][BM];
    __shared__ float Bs[BK][BN];

    const int tid = threadIdx.x;
    const int n0  = blockIdx.x * BN;
    const int m0  = blockIdx.y * BM;
    const int kb  = blockIdx.z * kChunk;
    const int ke  = (kb + kChunk < K) ? (kb + kChunk) : K;

    const int tc = tid % (BN / TN);
    const int tr = tid / (BN / TN);

    float acc[TM][TN];
    #pragma unroll
    for (int i = 0; i < TM; i++)
        #pragma unroll
        for (int j = 0; j < TN; j++) acc[i][j] = 0.0f;

    for (int k0 = kb; k0 < ke; k0 += BK) {
        #pragma unroll
        for (int i = tid; i < A4; i += THREADS) {
            int m  = i / KQ;
            int kq = i % KQ;
            float4 v = *(const float4*)&A[(size_t)(m0 + m) * lda + k0 + kq * 4];
            As[kq*4+0][m] = v.x; As[kq*4+1][m] = v.y;
            As[kq*4+2][m] = v.z; As[kq*4+3][m] = v.w;
        }
        #pragma unroll
        for (int i = tid; i < B4; i += THREADS) {
            int n  = i / KQ;
            int kq = i % KQ;
            float4 v = *(const float4*)&Bm[(size_t)(n0 + n) * ldb + k0 + kq * 4];
            Bs[kq*4+0][n] = v.x; Bs[kq*4+1][n] = v.y;
            Bs[kq*4+2][n] = v.z; Bs[kq*4+3][n] = v.w;
        }
        __syncthreads();

        #pragma unroll
        for (int kk = 0; kk < BK; kk++) {
            float a[TM], b[TN];
            #pragma unroll
            for (int i = 0; i < TM; i++) a[i] = As[kk][tr*TM + i];
            #pragma unroll
            for (int j = 0; j < TN; j++) b[j] = Bs[kk][tc*TN + j];
            #pragma unroll
            for (int i = 0; i < TM; i++)
                #pragma unroll
                for (int j = 0; j < TN; j++)
                    acc[i][j] = fmaf(a[i], b[j], acc[i][j]);
        }
        __syncthreads();
    }

    #pragma unroll
    for (int i = 0; i < TM; i++) {
        int m = m0 + tr*TM + i;
        #pragma unroll
        for (int j = 0; j < TN; j++) {
            int n = n0 + tc*TN + j;
            float v = acc[i][j];
            if (EPI == 0) {
                C[(size_t)m * ldc + n] = v;
            } else if (EPI == 1) {
                atomicAdd(&C[(size_t)m * ldc + n], v);
            } else {
                float x = v + bias[n];
                float r2 = fmaxf(x, 0.0f) + log1pf(__expf(-fabsf(x)));
                C[(size_t)m * ldc + n] = r2;
            }
        }
    }
}

// ---------------- conv window shift + SiLU ----------------
__global__ void conv_kernel(const float* __restrict__ cs_in,
                            const float* __restrict__ conv_w,
                            const float* __restrict__ conv_b,
                            float* __restrict__ cs_out)
{
    int idx = blockIdx.x * blockDim.x + threadIdx.x;
    int b = idx >> 13;
    int d = idx & (DINNER - 1);
    float4 cs = ((const float4*)cs_in)[idx];
    float4 w  = ((const float4*)conv_w)[d];
    float xi  = g_xz[(size_t)b * (2*DINNER) + d];
    float s = cs.y*w.x + cs.z*w.y + cs.w*w.z + xi*w.w + conv_b[d];
    float sig = 1.0f / (1.0f + __expf(-s));
    g_xc[idx] = s * sig;
    ((float4*)cs_out)[idx] = make_float4(cs.y, cs.z, cs.w, xi);
}

// ---------------- SSM state update + y (emits y as bf16 hi/lo) --------------
__global__ void ssm_kernel(const float* __restrict__ ssm_in,
                           const float* __restrict__ D_param,
                           float* __restrict__ ssm_out)
{
    __shared__ float bm[DSTATE], cm[DSTATE];
    const int b = blockIdx.y;
    const int d = blockIdx.x * blockDim.x + threadIdx.x;
    if (threadIdx.x < 2*DSTATE) {
        float v = g_xdb[b * XPN + DTRANK + threadIdx.x];
        if (threadIdx.x < DSTATE) bm[threadIdx.x] = v;
        else                      cm[threadIdx.x - DSTATE] = v;
    }
    __syncthreads();

    const int bd = b * DINNER + d;
    const float dtv = g_dt[bd];
    const float xcv = g_xc[bd];
    const float xdt = xcv * dtv;
    const size_t base = (size_t)bd * DSTATE;

    float yacc = 0.0f;
    #pragma unroll
    for (int n = 0; n < DSTATE; n += 4) {
        float4 a  = *(const float4*)&g_A[d * DSTATE + n];
        float4 st = *(const float4*)&ssm_in[base + n];
        float4 ns;
        ns.x = st.x * __expf(a.x * dtv) + xdt * bm[n+0];
        ns.y = st.y * __expf(a.y * dtv) + xdt * bm[n+1];
        ns.z = st.z * __expf(a.z * dtv) + xdt * bm[n+2];
        ns.w = st.w * __expf(a.w * dtv) + xdt * bm[n+3];
        yacc += ns.x * cm[n+0] + ns.y * cm[n+1] + ns.z * cm[n+2] + ns.w * cm[n+3];
        *(float4*)&ssm_out[base + n] = ns;
    }
    yacc += D_param[d] * xcv;
    float zv = g_xz[(size_t)b * (2*DINNER) + DINNER + d];
    yacc *= zv / (1.0f + __expf(-zv));

    __nv_bfloat16 h = __float2bfloat16(yacc);
    g_yhi[bd] = h;
    g_ylo[bd] = __float2bfloat16(yacc - __bfloat162float(h));
}

// ---------------- launch ----------------
extern "C" void kernel_launch(void* const* d_in, const int* in_sizes, int n_in,
                              void* d_out, int out_size)
{
    const float* x       = (const float*)d_in[0];
    const float* cs_in   = (const float*)d_in[1];
    const float* ssm_in  = (const float*)d_in[2];
    const float* W_in    = (const float*)d_in[3];
    const float* conv_w  = (const float*)d_in[4];
    const float* conv_b  = (const float*)d_in[5];
    const float* W_xproj = (const float*)d_in[6];
    const float* W_dt    = (const float*)d_in[7];
    const float* b_dt    = (const float*)d_in[8];
    const float* A_log   = (const float*)d_in[9];
    const float* D_param = (const float*)d_in[10];
    const float* W_out   = (const float*)d_in[11];

    float* out     = (float*)d_out;
    float* cs_out  = out + (size_t)BB * DMODEL;
    float* ssm_out = cs_out + (size_t)BB * DINNER * 4;

    void *p_xz, *p_xc, *p_xdb, *p_dt, *p_xhi, *p_xlo, *p_yhi, *p_ylo;
    cudaGetSymbolAddress(&p_xz,  g_xz);
    cudaGetSymbolAddress(&p_xc,  g_xc);
    cudaGetSymbolAddress(&p_xdb, g_xdb);
    cudaGetSymbolAddress(&p_dt,  g_dt);
    cudaGetSymbolAddress(&p_xhi, g_xhi);
    cudaGetSymbolAddress(&p_xlo, g_xlo);
    cudaGetSymbolAddress(&p_yhi, g_yhi);
    cudaGetSymbolAddress(&p_ylo, g_ylo);

    const int HSM = NSTAGE * STG_BYTES;   // 98304 bytes -> 2 CTAs/SM
    cudaFuncSetAttribute(hmma_gemm<0,1>, cudaFuncAttributeMaxDynamicSharedMemorySize, HSM);
    cudaFuncSetAttribute(hmma_gemm<1,4>, cudaFuncAttributeMaxDynamicSharedMemorySize, HSM);

    // launches 0-2, then GEMM1 as the 4th launch (ncu window profiles index 3)
    zero_kernel<<<(BB*XPN + 255)/256, 256>>>((float*)p_xdb, BB*XPN);
    zero_kernel<<<(BB*DMODEL + 255)/256, 256>>>(out, BB*DMODEL);
    split_bf16_kernel<<<(BB*DMODEL/4 + 255)/256, 256>>>(
        (const float4*)x, (__nv_bfloat162*)p_xhi, (__nv_bfloat162*)p_xlo, BB*DMODEL/4);

    // GEMM1: xz[256,16384] = x @ W_in^T   (B = W_in fp32 direct)
    hmma_gemm<0,1><<<dim3((2*DINNER)/GBN, BB/GBM, 1), 256, HSM>>>(
        (const __nv_bfloat16*)p_xhi, (const __nv_bfloat16*)p_xlo,
        W_in, (float*)p_xz, 2*DINNER, DMODEL);

    precompute_A_kernel<<<(DINNER*DSTATE + 255)/256, 256>>>(A_log);

    // conv + SiLU
    conv_kernel<<<(BB*DINNER)/256, 256>>>(cs_in, conv_w, conv_b, cs_out);

    // GEMM3: x_db[256,160] = xc @ W_xproj^T  (fp32, BK=32, split-K=16, atomic)
    sgemm_nt<64,32,32,4,4,1><<<dim3(XPN/32, BB/64, 16), 128>>>(
        (const float*)p_xc, DINNER, W_xproj, DINNER, (float*)p_xdb, XPN,
        BB, XPN, DINNER, DINNER/16, nullptr);

    // GEMM4: dt[256,8192] = softplus(x_db[:, :128] @ W_dt^T + b_dt)  (fp32, BK=32)
    sgemm_nt<64,64,32,4,4,2><<<dim3(DINNER/64, BB/64, 1), 256>>>(
        (const float*)p_xdb, XPN, W_dt, DTRANK, (float*)p_dt, DINNER,
        BB, DINNER, DTRANK, DTRANK, b_dt);

    // SSM update + y (emits yhi/ylo)
    ssm_kernel<<<dim3(DINNER/256, BB), 256>>>(ssm_in, D_param, ssm_out);

    // GEMM6: out[256,2048] = y @ W_out^T  (B = W_out fp32 direct, split-K=4, atomic)
    hmma_gemm<1,4><<<dim3(DMODEL/GBN, BB/GBM, 4), 256, HSM>>>(
        (const __nv_bfloat16*)p_yhi, (const __nv_bfloat16*)p_ylo,
        W_out, out, DMODEL, DINNER);
}